// round 15
// baseline (speedup 1.0000x reference)
#include <cuda_runtime.h>
#include <cuda_bf16.h>
#include <math.h>

#define BB    2
#define NN    2048
#define DIM   512
#define HH    8
#define DH    64
#define INNER 512
#define QKV3  1536
#define MROWS (BB*NN)      // 4096

typedef __nv_bfloat16 bf16;

// ---------------- device scratch (no allocation allowed) ----------------
__device__ bf16 g_x_h[MROWS * DIM],    g_x_l[MROWS * DIM];
__device__ bf16 g_wqkv_h[DIM * QKV3],  g_wqkv_l[DIM * QKV3];
__device__ bf16 g_wout_h[INNER * DIM], g_wout_l[INNER * DIM];

// key compaction + fused K|V buffer (K at col 0..511, V at col 512..1023)
__device__ int  g_cnt[BB];
__device__ int  g_idx[BB * NN];
__device__ bf16 g_kvc_h[BB * NN * 1024], g_kvc_l[BB * NN * 1024];
__device__ float g_xpart[BB * 8 * DIM];
__device__ float g_vmpart[BB * 8 * INNER];
__device__ float g_vmean[BB * INNER];
__device__ float g_dead[BB * DIM];

// query compaction
__device__ int  g_qcnt[BB];
__device__ int  g_qidx[BB * NN];
__device__ int  g_qpos[BB * NN];
__device__ bf16 g_qc_h[BB * NN * INNER], g_qc_l[BB * NN * INNER];
__device__ bf16 g_atc_h[BB * NN * INNER], g_atc_l[BB * NN * INNER];

// ---------------- helpers ----------------
__device__ __forceinline__ unsigned s2u(const void* p) {
    return (unsigned)__cvta_generic_to_shared(p);
}
__device__ __forceinline__ void ldsm4(unsigned* r, const void* p) {
    asm volatile("ldmatrix.sync.aligned.m8n8.x4.shared.b16 {%0,%1,%2,%3}, [%4];"
        : "=r"(r[0]), "=r"(r[1]), "=r"(r[2]), "=r"(r[3]) : "r"(s2u(p)));
}
__device__ __forceinline__ void ldsm4t(unsigned* r, const void* p) {
    asm volatile("ldmatrix.sync.aligned.m8n8.x4.trans.shared.b16 {%0,%1,%2,%3}, [%4];"
        : "=r"(r[0]), "=r"(r[1]), "=r"(r[2]), "=r"(r[3]) : "r"(s2u(p)));
}
__device__ __forceinline__ void cp16(void* s, const void* g) {
    asm volatile("cp.async.cg.shared.global [%0], [%1], 16;" :: "r"(s2u(s)), "l"(g));
}
__device__ __forceinline__ void cp_commit() { asm volatile("cp.async.commit_group;"); }
template<int N> __device__ __forceinline__ void cp_wait() {
    asm volatile("cp.async.wait_group %0;" :: "n"(N));
}
__device__ __forceinline__ void mma_bf16(float* c, const unsigned* a, unsigned b0, unsigned b1) {
    asm volatile(
        "mma.sync.aligned.m16n8k16.row.col.f32.bf16.bf16.f32 "
        "{%0,%1,%2,%3}, {%4,%5,%6,%7}, {%8,%9}, {%0,%1,%2,%3};"
        : "+f"(c[0]), "+f"(c[1]), "+f"(c[2]), "+f"(c[3])
        : "r"(a[0]), "r"(a[1]), "r"(a[2]), "r"(a[3]), "r"(b0), "r"(b1));
}
__device__ __forceinline__ unsigned pack2(bf16 a, bf16 b) {
    __nv_bfloat162 v; v.x = a; v.y = b;
    return *reinterpret_cast<unsigned*>(&v);
}
__device__ __forceinline__ void split1(float v, bf16& h, bf16& l) {
    h = __float2bfloat16(v);
    l = __float2bfloat16(v - __bfloat162float(h));
}
__device__ __forceinline__ void split4(const float4 v, uint2& ho, uint2& lo) {
    bf16 h0, l0, h1, l1, h2, l2, h3, l3;
    split1(v.x, h0, l0); split1(v.y, h1, l1);
    split1(v.z, h2, l2); split1(v.w, h3, l3);
    ho.x = pack2(h0, h1); ho.y = pack2(h2, h3);
    lo.x = pack2(l0, l1); lo.y = pack2(l2, l3);
}

// ---------------- prep: vectorized splits ----------------
__global__ void split_xw(const float* __restrict__ x, const float* __restrict__ wqkv)
{
    const int n1 = (MROWS * DIM) / 4, n2 = (DIM * QKV3) / 4;
    const int total = n1 + n2;
    for (int i = blockIdx.x * blockDim.x + threadIdx.x; i < total;
         i += gridDim.x * blockDim.x) {
        float4 v; bf16 *hi, *lo; int off;
        if (i < n1) { off = i * 4; v = *reinterpret_cast<const float4*>(&x[off]);
                      hi = g_x_h; lo = g_x_l; }
        else        { off = (i - n1) * 4; v = *reinterpret_cast<const float4*>(&wqkv[off]);
                      hi = g_wqkv_h; lo = g_wqkv_l; }
        uint2 ho, lw; split4(v, ho, lw);
        *reinterpret_cast<uint2*>(&hi[off]) = ho;
        *reinterpret_cast<uint2*>(&lo[off]) = lw;
    }
}
__global__ void split_wout(const float* __restrict__ wout)
{
    const int total = (INNER * DIM) / 4;
    for (int i = blockIdx.x * blockDim.x + threadIdx.x; i < total;
         i += gridDim.x * blockDim.x) {
        int off = i * 4;
        float4 v = *reinterpret_cast<const float4*>(&wout[off]);
        uint2 ho, lw; split4(v, ho, lw);
        *reinterpret_cast<uint2*>(&g_wout_h[off]) = ho;
        *reinterpret_cast<uint2*>(&g_wout_l[off]) = lw;
    }
}

// ---------------- fused compactions (parallel scan); grid (2, BB) -----------
__global__ void build_both(const int* __restrict__ mnp, const int* __restrict__ mbert)
{
    const int b = blockIdx.y;
    const bool isQ = (blockIdx.x == 1);
    const int tid = threadIdx.x;
    __shared__ int scan[256];

    int flags[8];
    int local = 0;
#pragma unroll
    for (int k = 0; k < 8; k++) {
        int j = tid * 8 + k;
        int f;
        if (isQ) f = (mnp[b * NN + j] == 1);
        else     f = (mnp[b * NN + j] == 1) && (mbert[b * NN + j] == 0);
        flags[k] = f; local += f;
    }
    scan[tid] = local;
    __syncthreads();
#pragma unroll
    for (int off = 1; off < 256; off <<= 1) {
        int add = (tid >= off) ? scan[tid - off] : 0;
        __syncthreads();
        scan[tid] += add;
        __syncthreads();
    }
    const int tot = scan[255];
    int o = scan[tid] - local;
    if (isQ) {
        if (tid == 0) g_qcnt[b] = tot;
#pragma unroll
        for (int k = 0; k < 8; k++) {
            int j = tid * 8 + k;
            if (flags[k]) { g_qidx[b * NN + o] = j; g_qpos[b * NN + j] = o; o++; }
            else g_qpos[b * NN + j] = -1;
        }
        for (int i = tot + tid; i < NN; i += 256) g_qidx[b * NN + i] = 0;
    } else {
        if (tid == 0) g_cnt[b] = tot;
#pragma unroll
        for (int k = 0; k < 8; k++) {
            if (flags[k]) g_idx[b * NN + (o++)] = tid * 8 + k;
        }
        for (int i = tot + tid; i < NN; i += 256) g_idx[b * NN + i] = 0;
    }
}

// ---------------- partial sums of x rows: grid (DIM/64, BB, 8) --------------
__global__ void meanx_part(const float* __restrict__ x)
{
    const int b = blockIdx.y;
    const int z = blockIdx.z;
    const int d = blockIdx.x * 64 + threadIdx.x;
    const int yg = threadIdx.y;
    float s = 0.0f;
    const int r0 = z * 256;
    for (int j = yg; j < 256; j += 8)
        s += x[((size_t)(b * NN + r0 + j)) * DIM + d];
    __shared__ float red[8][64];
    red[yg][threadIdx.x] = s;
    __syncthreads();
    if (yg == 0) {
        float tot = 0.0f;
#pragma unroll
        for (int i = 0; i < 8; i++) tot += red[i][threadIdx.x];
        g_xpart[(b * 8 + z) * DIM + d] = tot;
    }
}

// ---------------- vmean partials: grid (INNER/64, BB, 8 d-chunks) -----------
__global__ void vmean_part(const float* __restrict__ Wqkv)
{
    const int b = blockIdx.y;
    const int z = blockIdx.z;
    const int col = blockIdx.x * 64 + threadIdx.x;
    const int yg = threadIdx.y;
    const int tid = yg * 64 + threadIdx.x;
    __shared__ float xm[64];
    if (tid < 64) {
        float s = 0.0f;
#pragma unroll
        for (int zz = 0; zz < 8; zz++) s += g_xpart[(b * 8 + zz) * DIM + z * 64 + tid];
        xm[tid] = s * (1.0f / NN);
    }
    __syncthreads();
    float s = 0.0f;
#pragma unroll
    for (int j = yg; j < 64; j += 8)
        s += xm[j] * Wqkv[(size_t)(z * 64 + j) * QKV3 + 2 * INNER + col];
    __shared__ float red[8][64];
    red[yg][threadIdx.x] = s;
    __syncthreads();
    if (yg == 0) {
        float tot = 0.0f;
#pragma unroll
        for (int i = 0; i < 8; i++) tot += red[i][threadIdx.x];
        g_vmpart[(b * 8 + z) * INNER + col] = tot;
    }
}

// ---------------- fused vmean combine + dead vector; grid (DIM/64, BB) ------
__global__ void deadvec_fused(const float* __restrict__ Wout,
                              const float* __restrict__ bias)
{
    const int b = blockIdx.y;
    const int col = blockIdx.x * 64 + threadIdx.x;
    const int yg = threadIdx.y;
    const int tid = yg * 64 + threadIdx.x;
    __shared__ float vm[INNER];
    if (tid < INNER) {
        float s = 0.0f;
#pragma unroll
        for (int z = 0; z < 8; z++) s += g_vmpart[(b * 8 + z) * INNER + tid];
        vm[tid] = s;
        if (blockIdx.x == 0) g_vmean[b * INNER + tid] = s;
    }
    __syncthreads();
    float s = 0.0f;
#pragma unroll 4
    for (int d = yg; d < INNER; d += 16)
        s += vm[d] * Wout[(size_t)d * DIM + col];
    __shared__ float red[16][64];
    red[yg][threadIdx.x] = s;
    __syncthreads();
    if (yg == 0) {
        float tot = bias[col];
#pragma unroll
        for (int i = 0; i < 16; i++) tot += red[i][threadIdx.x];
        g_dead[b * DIM + col] = tot;
    }
}

// ---------------- cnt==0 fallback: fill compacted att rows with vmean -------
// Only active when a batch has zero surviving keys (never overlaps attn's
// writes: attn returns without writing in that case).
__global__ void atc_vmean_fill()
{
    const int b = blockIdx.y;
    if (g_cnt[b] != 0) return;
    const int qcnt = g_qcnt[b];
    const int qpad = (qcnt + 127) & ~127;
    const int i = blockIdx.x;
    if (i >= qpad) return;
    const int tid = threadIdx.x;            // 128 thr x 4 elems
    const size_t base = ((size_t)(b * NN + i)) * INNER + tid * 4;
    bf16 h0, l0, h1, l1, h2, l2, h3, l3;
    split1(g_vmean[b * INNER + tid * 4 + 0], h0, l0);
    split1(g_vmean[b * INNER + tid * 4 + 1], h1, l1);
    split1(g_vmean[b * INNER + tid * 4 + 2], h2, l2);
    split1(g_vmean[b * INNER + tid * 4 + 3], h3, l3);
    *reinterpret_cast<unsigned*>(&g_atc_h[base])     = pack2(h0, h1);
    *reinterpret_cast<unsigned*>(&g_atc_h[base + 2]) = pack2(h2, h3);
    *reinterpret_cast<unsigned*>(&g_atc_l[base])     = pack2(l0, l1);
    *reinterpret_cast<unsigned*>(&g_atc_l[base + 2]) = pack2(l2, l3);
}

// ---------------- fill dead output rows -------------------------------------
__global__ void dead_fill(float* __restrict__ out)
{
    const int b = blockIdx.y;
    const int i = blockIdx.x;
    if (g_qpos[b * NN + i] >= 0) return;
    const int tid = threadIdx.x;
    *reinterpret_cast<float4*>(&out[((size_t)(b * NN + i)) * DIM + tid * 4]) =
        *reinterpret_cast<const float4*>(&g_dead[b * DIM + tid * 4]);
}

// ---------------------------------------------------------------------------
// bf16x3 GEMM body, 128x128 block, BK=32, 512 thr (16 warps; warp tile 32x32).
// ---------------------------------------------------------------------------
#define GALD 40
#define GBLD 136
#define G_SA(buf,hl) (sm + ((buf)*2 + (hl)) * (128*GALD))
#define G_SB(buf,hl) (sm + 4*128*GALD + ((buf)*2 + (hl)) * (32*GBLD))
#define GEMM_SMEM_BYTES ((4*128*GALD + 4*32*GBLD) * 2)

__device__ __forceinline__ void gemm_body(bf16* sm, int bm, int bn,
                                          const bf16* __restrict__ Ah,
                                          const bf16* __restrict__ Al,
                                          int lda,
                                          const int* __restrict__ ridx,
                                          const int* __restrict__ cntp,
                                          const bf16* __restrict__ Bh,
                                          const bf16* __restrict__ Bl,
                                          int ldb,
                                          const float* __restrict__ bias,
                                          float* __restrict__ outf,
                                          bf16* __restrict__ outh,
                                          bf16* __restrict__ outl,
                                          int ldo,
                                          const int* __restrict__ oidx,
                                          int K, int mode)
{
    const int b  = bm >> 11;                 // NN = 2048
    const int lm = bm & (NN - 1);
    const int bbase = b * NN;

    int cntv = NN;
    if (cntp) {
        cntv = cntp[b];
        if (lm >= ((cntv + 127) & ~127)) return;
    }

    const int tid = threadIdx.x;
    const int warp = tid >> 5;
    const int lane = tid & 31;
    const int g = lane >> 2;
    const int t = lane & 3;
    const int rowbase = (warp & 3) * 32;
    const int colbase = (warp >> 2) * 32;

    float acc[2][4][4];
#pragma unroll
    for (int mt = 0; mt < 2; mt++)
#pragma unroll
        for (int nt = 0; nt < 4; nt++)
#pragma unroll
            for (int i = 0; i < 4; i++) acc[mt][nt][i] = 0.0f;

    const int tile = lane >> 3;
    const int trow = lane & 7;

    const int arow = tid >> 2;
    const int akch = (tid & 3) * 8;
    int agrow;
    if (ridx) agrow = bbase + ridx[bbase + lm + arow];
    else      agrow = bm + arow;

    auto prefetch = [&](int buf, int k0) {
        {
            size_t go = (size_t)agrow * lda + k0 + akch;
            cp16(&G_SA(buf, 0)[arow * GALD + akch], &Ah[go]);
            cp16(&G_SA(buf, 1)[arow * GALD + akch], &Al[go]);
        }
        {
            int kr = tid >> 4, nch = (tid & 15) * 8;
            size_t go = (size_t)(k0 + kr) * ldb + bn + nch;
            cp16(&G_SB(buf, 0)[kr * GBLD + nch], &Bh[go]);
            cp16(&G_SB(buf, 1)[kr * GBLD + nch], &Bl[go]);
        }
    };

    prefetch(0, 0);
    cp_commit();

    const int NIT = K / 32;
    int buf = 0;
    for (int it = 0; it < NIT; it++) {
        if (it + 1 < NIT) { prefetch(buf ^ 1, (it + 1) * 32); cp_commit(); cp_wait<1>(); }
        else cp_wait<0>();
        __syncthreads();

        const bf16* As_h = G_SA(buf, 0);
        const bf16* As_l = G_SA(buf, 1);
        const bf16* Bs_h = G_SB(buf, 0);
        const bf16* Bs_l = G_SB(buf, 1);

#pragma unroll
        for (int kc = 0; kc < 2; kc++) {
            unsigned ah[2][4], al[2][4];
            const int amrow = (tile & 1) * 8 + trow;
            const int akoff = kc * 16 + (tile >> 1) * 8;
#pragma unroll
            for (int mt = 0; mt < 2; mt++) {
                ldsm4(ah[mt], &As_h[(rowbase + mt * 16 + amrow) * GALD + akoff]);
                ldsm4(al[mt], &As_l[(rowbase + mt * 16 + amrow) * GALD + akoff]);
            }
            const int bkrow = kc * 16 + (tile & 1) * 8 + trow;
            unsigned bh[2][4], bl[2][4];
#pragma unroll
            for (int ntp = 0; ntp < 2; ntp++) {
                const int bncol = colbase + ntp * 16 + (tile >> 1) * 8;
                ldsm4t(bh[ntp], &Bs_h[bkrow * GBLD + bncol]);
                ldsm4t(bl[ntp], &Bs_l[bkrow * GBLD + bncol]);
            }
#pragma unroll
            for (int mt = 0; mt < 2; mt++)
#pragma unroll
                for (int ntp = 0; ntp < 2; ntp++)
#pragma unroll
                    for (int q = 0; q < 2; q++)
                        mma_bf16(acc[mt][ntp * 2 + q], ah[mt], bh[ntp][q * 2], bh[ntp][q * 2 + 1]);
#pragma unroll
            for (int mt = 0; mt < 2; mt++)
#pragma unroll
                for (int ntp = 0; ntp < 2; ntp++)
#pragma unroll
                    for (int q = 0; q < 2; q++)
                        mma_bf16(acc[mt][ntp * 2 + q], ah[mt], bl[ntp][q * 2], bl[ntp][q * 2 + 1]);
#pragma unroll
            for (int mt = 0; mt < 2; mt++)
#pragma unroll
                for (int ntp = 0; ntp < 2; ntp++)
#pragma unroll
                    for (int q = 0; q < 2; q++)
                        mma_bf16(acc[mt][ntp * 2 + q], al[mt], bh[ntp][q * 2], bh[ntp][q * 2 + 1]);
        }
        __syncthreads();
        buf ^= 1;
    }

#pragma unroll
    for (int mt = 0; mt < 2; mt++) {
        const int lr0 = lm + rowbase + mt * 16 + g;
        const int lr1 = lr0 + 8;
#pragma unroll
        for (int nt = 0; nt < 4; nt++) {
            const int c0 = bn + colbase + nt * 8 + 2 * t;
            float v0 = acc[mt][nt][0], v1 = acc[mt][nt][1];
            float v2 = acc[mt][nt][2], v3 = acc[mt][nt][3];
            if (mode == 0) {
                float b0 = bias[c0], b1 = bias[c0 + 1];
                if (lr0 < cntv) {
                    int orow = bbase + oidx[bbase + lr0];
                    *reinterpret_cast<float2*>(&outf[(size_t)orow * ldo + c0]) =
                        make_float2(v0 + b0, v1 + b1);
                }
                if (lr1 < cntv) {
                    int orow = bbase + oidx[bbase + lr1];
                    *reinterpret_cast<float2*>(&outf[(size_t)orow * ldo + c0]) =
                        make_float2(v2 + b0, v3 + b1);
                }
            } else {
                bf16 h0, l0, h1, l1, h2, l2, h3, l3;
                split1(v0, h0, l0); split1(v1, h1, l1);
                split1(v2, h2, l2); split1(v3, h3, l3);
                const size_t r0o = (size_t)(bbase + lr0) * ldo + c0;
                const size_t r1o = (size_t)(bbase + lr1) * ldo + c0;
                *reinterpret_cast<unsigned*>(&outh[r0o]) = pack2(h0, h1);
                *reinterpret_cast<unsigned*>(&outl[r0o]) = pack2(l0, l1);
                *reinterpret_cast<unsigned*>(&outh[r1o]) = pack2(h2, h3);
                *reinterpret_cast<unsigned*>(&outl[r1o]) = pack2(l2, l3);
            }
        }
    }
}

// ---- fused projection GEMM: x<4 -> Q (alive rows), x>=4 -> K|V (key rows) --
__global__ __launch_bounds__(512, 1) void gemm_proj()
{
    extern __shared__ bf16 sm[];
    const int bm = blockIdx.y * 128;
    if (blockIdx.x < 4) {
        gemm_body(sm, bm, blockIdx.x * 128,
                  g_x_h, g_x_l, DIM, g_qidx, g_qcnt,
                  g_wqkv_h, g_wqkv_l, QKV3, nullptr,
                  nullptr, g_qc_h, g_qc_l, INNER, nullptr, DIM, 1);
    } else {
        gemm_body(sm, bm, (blockIdx.x - 4) * 128,
                  g_x_h, g_x_l, DIM, g_idx, g_cnt,
                  g_wqkv_h + INNER, g_wqkv_l + INNER, QKV3, nullptr,
                  nullptr, g_kvc_h, g_kvc_l, 1024, nullptr, DIM, 1);
    }
}

// ---- output GEMM: compacted att rows @ W_out + bias, scatter rows ----------
__global__ __launch_bounds__(512, 1) void gemm_out(const float* __restrict__ bias,
                                                   float* __restrict__ out)
{
    extern __shared__ bf16 sm[];
    gemm_body(sm, blockIdx.y * 128, blockIdx.x * 128,
              g_atc_h, g_atc_l, INNER, nullptr, g_qcnt,
              g_wout_h, g_wout_l, DIM, bias,
              out, nullptr, nullptr, DIM, g_qidx, INNER, 0);
}

// ---------------------------------------------------------------------------
// Attention over compacted Q rows and fused K|V buffer.
// 256 thr (8 warps), 128 q-rows/block, 128-key tiles. Q frags in registers.
// ---------------------------------------------------------------------------
#define ASLD 72
#define A_Q(hl)     (sm + (hl) * (128 * ASLD))
#define A_KV(buf,m) (sm + 2 * 128 * ASLD + ((buf) * 4 + (m)) * (128 * ASLD))
#define ATT_BF16_TOT (2 * 128 * ASLD + 8 * 128 * ASLD)
#define ATT_SMEM_BYTES (ATT_BF16_TOT * 2)

__global__ __launch_bounds__(256, 1) void attn_mma()
{
    extern __shared__ char smraw[];
    bf16* sm = reinterpret_cast<bf16*>(smraw);

    const int b  = blockIdx.y >> 3;
    const int h  = blockIdx.y & 7;
    const int q0 = blockIdx.x * 128;

    const int cnt = g_cnt[b];
    if (cnt == 0) return;                       // handled by atc_vmean_fill

    const int qcnt = g_qcnt[b];
    const int qpad = (qcnt + 127) & ~127;
    if (q0 >= qpad) return;

    const int ntiles = (cnt + 127) >> 7;        // 128-key tiles

    const int tid = threadIdx.x;
    const int warp = tid >> 5;
    const int lane = tid & 31;
    const int g = lane >> 2;
    const int t = lane & 3;
    const int rb = warp * 16;
    const float scale = 0.125f;
    const int tile = lane >> 3;
    const int trow = lane & 7;

    // Q prefetch: 128 rows x 64 dims, hi+lo
#pragma unroll
    for (int j = 0; j < 4; j++) {
        int c = tid * 4 + j;
        int row = c >> 3, dch = (c & 7) * 8;
        size_t base = (size_t)(b * NN + q0 + row) * INNER + h * 64 + dch;
        cp16(&A_Q(0)[row * ASLD + dch], &g_qc_h[base]);
        cp16(&A_Q(1)[row * ASLD + dch], &g_qc_l[base]);
    }
    cp_commit();

    // KV prefetch: 128 rows x 64 dims x 4 arrays
    auto pref = [&](int buf, int kt0) {
#pragma unroll
        for (int j = 0; j < 4; j++) {
            int c = tid * 4 + j;                // 0..1023
            int row = c >> 3, dch = (c & 7) * 8;
            size_t base = ((size_t)(b * NN + kt0 + row)) * 1024 + h * 64 + dch;
            cp16(&A_KV(buf, 0)[row * ASLD + dch], &g_kvc_h[base]);
            cp16(&A_KV(buf, 1)[row * ASLD + dch], &g_kvc_l[base]);
            cp16(&A_KV(buf, 2)[row * ASLD + dch], &g_kvc_h[base + 512]);
            cp16(&A_KV(buf, 3)[row * ASLD + dch], &g_kvc_l[base + 512]);
        }
    };

    pref(0, 0);
    cp_commit();

    float O[8][4];
#pragma unroll
    for (int nt = 0; nt < 8; nt++)
#pragma unroll
        for (int i = 0; i < 4; i++) O[nt][i] = 0.0f;
    float lsum0 = 0.0f, lsum8 = 0.0f;

    unsigned aqh[4][4], aql[4][4];
    bool qloaded = false;
    const int qr = rb + (tile & 1) * 8 + trow;

    int buf = 0;
    for (int kt = 0; kt < ntiles; kt++) {
        const int kt0 = kt * 128;
        if (kt + 1 < ntiles) { pref(buf ^ 1, (kt + 1) * 128); cp_commit(); cp_wait<1>(); }
        else cp_wait<0>();
        __syncthreads();

        if (!qloaded) {
            qloaded = true;
#pragma unroll
            for (int kc = 0; kc < 4; kc++) {
                ldsm4(aqh[kc], &A_Q(0)[qr * ASLD + kc * 16 + (tile >> 1) * 8]);
                ldsm4(aql[kc], &A_Q(1)[qr * ASLD + kc * 16 + (tile >> 1) * 8]);
            }
        }

        const bf16* KHs = A_KV(buf, 0);
        const bf16* KLs = A_KV(buf, 1);
        const bf16* VHs = A_KV(buf, 2);
        const bf16* VLs = A_KV(buf, 3);

        unsigned pah[8][4], pal[8][4];          // 8 x 16-key chunks

#pragma unroll
        for (int half = 0; half < 4; half++) {  // 4 halves of 32 keys
            float sc[4][4];
#pragma unroll
            for (int nt = 0; nt < 4; nt++)
#pragma unroll
                for (int i = 0; i < 4; i++) sc[nt][i] = 0.0f;

#pragma unroll
            for (int kc = 0; kc < 4; kc++) {
                const int koff = kc * 16 + (tile & 1) * 8;
                unsigned kbh[2][4], kbl[2][4];
#pragma unroll
                for (int ntp = 0; ntp < 2; ntp++) {
                    const int nrow = (half * 2 + ntp) * 16 + (tile >> 1) * 8 + trow;
                    ldsm4(kbh[ntp], &KHs[nrow * ASLD + koff]);
                    ldsm4(kbl[ntp], &KLs[nrow * ASLD + koff]);
                }
#pragma unroll
                for (int ntp = 0; ntp < 2; ntp++)
#pragma unroll
                    for (int q = 0; q < 2; q++)
                        mma_bf16(sc[ntp * 2 + q], aqh[kc], kbh[ntp][q * 2], kbh[ntp][q * 2 + 1]);
#pragma unroll
                for (int ntp = 0; ntp < 2; ntp++)
#pragma unroll
                    for (int q = 0; q < 2; q++)
                        mma_bf16(sc[ntp * 2 + q], aqh[kc], kbl[ntp][q * 2], kbl[ntp][q * 2 + 1]);
#pragma unroll
                for (int ntp = 0; ntp < 2; ntp++)
#pragma unroll
                    for (int q = 0; q < 2; q++)
                        mma_bf16(sc[ntp * 2 + q], aql[kc], kbh[ntp][q * 2], kbh[ntp][q * 2 + 1]);
            }

#pragma unroll
            for (int ntl = 0; ntl < 4; ntl++) {
                const int nt = half * 4 + ntl;          // 0..15 (8-key units)
                const int kch = nt >> 1, q = nt & 1;
                const int colg = kt0 + nt * 8 + 2 * t;
                const bool v0c = colg < cnt;
                const bool v1c = colg + 1 < cnt;
                float p0 = v0c ? __expf(sc[ntl][0] * scale) : 0.0f;
                float p1 = v1c ? __expf(sc[ntl][1] * scale) : 0.0f;
                float p2 = v0c ? __expf(sc[ntl][2] * scale) : 0.0f;
                float p3 = v1c ? __expf(sc[ntl][3] * scale) : 0.0f;
                lsum0 += p0 + p1;
                lsum8 += p2 + p3;
                bf16 h0, l0, h1, l1, h2, l2, h3, l3;
                split1(p0, h0, l0); split1(p1, h1, l1);
                split1(p2, h2, l2); split1(p3, h3, l3);
                pah[kch][q * 2 + 0] = pack2(h0, h1);
                pah[kch][q * 2 + 1] = pack2(h2, h3);
                pal[kch][q * 2 + 0] = pack2(l0, l1);
                pal[kch][q * 2 + 1] = pack2(l2, l3);
            }
        }

        // ---- PV over 8 key chunks ----
#pragma unroll
        for (int kch = 0; kch < 8; kch++) {
            const int keyrow = kch * 16 + (tile & 1) * 8 + trow;
            unsigned vh[4][4], vl[4][4];
#pragma unroll
            for (int dp = 0; dp < 4; dp++) {
                const int dcol = dp * 16 + (tile >> 1) * 8;
                ldsm4t(vh[dp], &VHs[keyrow * ASLD + dcol]);
                ldsm4t(vl[dp], &VLs[keyrow * ASLD + dcol]);
            }
#pragma unroll
            for (int dp = 0; dp < 4; dp++)
#pragma unroll
                for (int q = 0; q < 2; q++)
                    mma_bf16(O[dp * 2 + q], pah[kch], vh[dp][q * 2], vh[dp][q * 2 + 1]);
#pragma unroll
            for (int dp = 0; dp < 4; dp++)
#pragma unroll
                for (int q = 0; q < 2; q++)
                    mma_bf16(O[dp * 2 + q], pah[kch], vl[dp][q * 2], vl[dp][q * 2 + 1]);
#pragma unroll
            for (int dp = 0; dp < 4; dp++)
#pragma unroll
                for (int q = 0; q < 2; q++)
                    mma_bf16(O[dp * 2 + q], pal[kch], vh[dp][q * 2], vh[dp][q * 2 + 1]);
        }
        __syncthreads();
        buf ^= 1;
    }

    // epilogue: quad-reduce l, normalize, split-store
    lsum0 += __shfl_xor_sync(0xffffffffu, lsum0, 1);
    lsum0 += __shfl_xor_sync(0xffffffffu, lsum0, 2);
    lsum8 += __shfl_xor_sync(0xffffffffu, lsum8, 1);
    lsum8 += __shfl_xor_sync(0xffffffffu, lsum8, 2);
    const float inv0 = 1.0f / lsum0;
    const float inv8 = 1.0f / lsum8;

    const size_t row0 = (size_t)(b * NN + q0 + rb + g);
    const size_t row8 = row0 + 8;
#pragma unroll
    for (int nt = 0; nt < 8; nt++) {
        const int d = h * 64 + nt * 8 + 2 * t;
        float v0 = O[nt][0] * inv0, v1 = O[nt][1] * inv0;
        float v2 = O[nt][2] * inv8, v3 = O[nt][3] * inv8;
        bf16 h0, l0, h1, l1, h2, l2, h3, l3;
        split1(v0, h0, l0); split1(v1, h1, l1);
        split1(v2, h2, l2); split1(v3, h3, l3);
        *reinterpret_cast<unsigned*>(&g_atc_h[row0 * INNER + d]) = pack2(h0, h1);
        *reinterpret_cast<unsigned*>(&g_atc_l[row0 * INNER + d]) = pack2(l0, l1);
        *reinterpret_cast<unsigned*>(&g_atc_h[row8 * INNER + d]) = pack2(h2, h3);
        *reinterpret_cast<unsigned*>(&g_atc_l[row8 * INNER + d]) = pack2(l2, l3);
    }
}

// ---------------------------------------------------------------------------
extern "C" void kernel_launch(void* const* d_in, const int* in_sizes, int n_in,
                              void* d_out, int out_size)
{
    const float* x     = (const float*)d_in[0];
    const int*   mnp   = (const int*)d_in[1];
    const int*   mbert = (const int*)d_in[2];
    const float* Wqkv  = (const float*)d_in[3];
    const float* Wout  = (const float*)d_in[4];
    const float* bout  = (const float*)d_in[5];
    float* out = (float*)d_out;

    cudaFuncSetAttribute(gemm_proj, cudaFuncAttributeMaxDynamicSharedMemorySize,
                         GEMM_SMEM_BYTES);
    cudaFuncSetAttribute(gemm_out, cudaFuncAttributeMaxDynamicSharedMemorySize,
                         GEMM_SMEM_BYTES);
    cudaFuncSetAttribute(attn_mma, cudaFuncAttributeMaxDynamicSharedMemorySize,
                         ATT_SMEM_BYTES);

    cudaStream_t s2;
    cudaStreamCreateWithFlags(&s2, cudaStreamNonBlocking);
    cudaEvent_t e0, e_bb, e_wout, e_df;
    cudaEventCreateWithFlags(&e0,     cudaEventDisableTiming);
    cudaEventCreateWithFlags(&e_bb,   cudaEventDisableTiming);
    cudaEventCreateWithFlags(&e_wout, cudaEventDisableTiming);
    cudaEventCreateWithFlags(&e_df,   cudaEventDisableTiming);

    // fork
    cudaEventRecord(e0, 0);
    cudaStreamWaitEvent(s2, e0, 0);

    // main stream: split x+Wqkv (vectorized)
    split_xw<<<1024, 256>>>(x, Wqkv);

    // side stream: compactions + mean chain + cnt==0 fixup + Wout split + dead fill
    build_both<<<dim3(2, BB), 256, 0, s2>>>(mnp, mbert);
    cudaEventRecord(e_bb, s2);
    meanx_part<<<dim3(DIM / 64, BB, 8), dim3(64, 8), 0, s2>>>(x);
    vmean_part<<<dim3(INNER / 64, BB, 8), dim3(64, 8), 0, s2>>>(Wqkv);
    deadvec_fused<<<dim3(DIM / 64, BB), dim3(64, 16), 0, s2>>>(Wout, bout);
    atc_vmean_fill<<<dim3(NN, BB), 128, 0, s2>>>();
    split_wout<<<128, 256, 0, s2>>>(Wout);
    cudaEventRecord(e_wout, s2);
    dead_fill<<<dim3(NN, BB), 128, 0, s2>>>(out);
    cudaEventRecord(e_df, s2);

    // main stream: projections (needs compaction indices only)
    cudaStreamWaitEvent(0, e_bb, 0);
    gemm_proj<<<dim3(12, MROWS / 128), 512, GEMM_SMEM_BYTES>>>();

    // attention (no longer depends on the mean chain)
    attn_mma<<<dim3(NN / 128, BB * HH), 256, ATT_SMEM_BYTES>>>();

    // output projection (needs Wout split + cnt==0 fixup, both covered by e_wout)
    cudaStreamWaitEvent(0, e_wout, 0);
    gemm_out<<<dim3(DIM / 128, MROWS / 128), 512, GEMM_SMEM_BYTES>>>(bout, out);

    // join
    cudaStreamWaitEvent(0, e_df, 0);
}

// round 16
// speedup vs baseline: 1.0462x; 1.0462x over previous
#include <cuda_runtime.h>
#include <cuda_bf16.h>
#include <math.h>

#define BB    2
#define NN    2048
#define DIM   512
#define HH    8
#define DH    64
#define INNER 512
#define QKV3  1536
#define MROWS (BB*NN)      // 4096

typedef __nv_bfloat16 bf16;

// ---------------- device scratch (no allocation allowed) ----------------
__device__ bf16 g_x_h[MROWS * DIM],    g_x_l[MROWS * DIM];
__device__ bf16 g_wqkv_h[DIM * QKV3],  g_wqkv_l[DIM * QKV3];
__device__ bf16 g_wout_h[INNER * DIM], g_wout_l[INNER * DIM];

// key compaction + fused K|V buffer (K at col 0..511, V at col 512..1023)
__device__ int  g_cnt[BB];
__device__ int  g_idx[BB * NN];
__device__ bf16 g_kvc_h[BB * NN * 1024], g_kvc_l[BB * NN * 1024];
__device__ float g_xpart[BB * 8 * DIM];
__device__ float g_vmpart[BB * 8 * INNER];
__device__ float g_vmean[BB * INNER];
__device__ float g_dead[BB * DIM];

// query compaction
__device__ int  g_qcnt[BB];
__device__ int  g_qidx[BB * NN];
__device__ int  g_qpos[BB * NN];
__device__ bf16 g_qc_h[BB * NN * INNER], g_qc_l[BB * NN * INNER];
__device__ bf16 g_atc_h[BB * NN * INNER], g_atc_l[BB * NN * INNER];

// ---------------- helpers ----------------
__device__ __forceinline__ unsigned s2u(const void* p) {
    return (unsigned)__cvta_generic_to_shared(p);
}
__device__ __forceinline__ void ldsm4(unsigned* r, const void* p) {
    asm volatile("ldmatrix.sync.aligned.m8n8.x4.shared.b16 {%0,%1,%2,%3}, [%4];"
        : "=r"(r[0]), "=r"(r[1]), "=r"(r[2]), "=r"(r[3]) : "r"(s2u(p)));
}
__device__ __forceinline__ void ldsm4t(unsigned* r, const void* p) {
    asm volatile("ldmatrix.sync.aligned.m8n8.x4.trans.shared.b16 {%0,%1,%2,%3}, [%4];"
        : "=r"(r[0]), "=r"(r[1]), "=r"(r[2]), "=r"(r[3]) : "r"(s2u(p)));
}
__device__ __forceinline__ void cp16(void* s, const void* g) {
    asm volatile("cp.async.cg.shared.global [%0], [%1], 16;" :: "r"(s2u(s)), "l"(g));
}
__device__ __forceinline__ void cp_commit() { asm volatile("cp.async.commit_group;"); }
template<int N> __device__ __forceinline__ void cp_wait() {
    asm volatile("cp.async.wait_group %0;" :: "n"(N));
}
__device__ __forceinline__ void mma_bf16(float* c, const unsigned* a, unsigned b0, unsigned b1) {
    asm volatile(
        "mma.sync.aligned.m16n8k16.row.col.f32.bf16.bf16.f32 "
        "{%0,%1,%2,%3}, {%4,%5,%6,%7}, {%8,%9}, {%0,%1,%2,%3};"
        : "+f"(c[0]), "+f"(c[1]), "+f"(c[2]), "+f"(c[3])
        : "r"(a[0]), "r"(a[1]), "r"(a[2]), "r"(a[3]), "r"(b0), "r"(b1));
}
__device__ __forceinline__ unsigned pack2(bf16 a, bf16 b) {
    __nv_bfloat162 v; v.x = a; v.y = b;
    return *reinterpret_cast<unsigned*>(&v);
}
__device__ __forceinline__ void split1(float v, bf16& h, bf16& l) {
    h = __float2bfloat16(v);
    l = __float2bfloat16(v - __bfloat162float(h));
}
__device__ __forceinline__ void split4(const float4 v, uint2& ho, uint2& lo) {
    bf16 h0, l0, h1, l1, h2, l2, h3, l3;
    split1(v.x, h0, l0); split1(v.y, h1, l1);
    split1(v.z, h2, l2); split1(v.w, h3, l3);
    ho.x = pack2(h0, h1); ho.y = pack2(h2, h3);
    lo.x = pack2(l0, l1); lo.y = pack2(l2, l3);
}

// ---------------- prep: vectorized splits ----------------
__global__ void split_xw(const float* __restrict__ x, const float* __restrict__ wqkv)
{
    const int n1 = (MROWS * DIM) / 4, n2 = (DIM * QKV3) / 4;
    const int total = n1 + n2;
    for (int i = blockIdx.x * blockDim.x + threadIdx.x; i < total;
         i += gridDim.x * blockDim.x) {
        float4 v; bf16 *hi, *lo; int off;
        if (i < n1) { off = i * 4; v = *reinterpret_cast<const float4*>(&x[off]);
                      hi = g_x_h; lo = g_x_l; }
        else        { off = (i - n1) * 4; v = *reinterpret_cast<const float4*>(&wqkv[off]);
                      hi = g_wqkv_h; lo = g_wqkv_l; }
        uint2 ho, lw; split4(v, ho, lw);
        *reinterpret_cast<uint2*>(&hi[off]) = ho;
        *reinterpret_cast<uint2*>(&lo[off]) = lw;
    }
}
__global__ void split_wout(const float* __restrict__ wout)
{
    const int total = (INNER * DIM) / 4;
    for (int i = blockIdx.x * blockDim.x + threadIdx.x; i < total;
         i += gridDim.x * blockDim.x) {
        int off = i * 4;
        float4 v = *reinterpret_cast<const float4*>(&wout[off]);
        uint2 ho, lw; split4(v, ho, lw);
        *reinterpret_cast<uint2*>(&g_wout_h[off]) = ho;
        *reinterpret_cast<uint2*>(&g_wout_l[off]) = lw;
    }
}

// ---------------- fused compactions (parallel scan); grid (2, BB) -----------
__global__ void build_both(const int* __restrict__ mnp, const int* __restrict__ mbert)
{
    const int b = blockIdx.y;
    const bool isQ = (blockIdx.x == 1);
    const int tid = threadIdx.x;
    __shared__ int scan[256];

    int flags[8];
    int local = 0;
#pragma unroll
    for (int k = 0; k < 8; k++) {
        int j = tid * 8 + k;
        int f;
        if (isQ) f = (mnp[b * NN + j] == 1);
        else     f = (mnp[b * NN + j] == 1) && (mbert[b * NN + j] == 0);
        flags[k] = f; local += f;
    }
    scan[tid] = local;
    __syncthreads();
#pragma unroll
    for (int off = 1; off < 256; off <<= 1) {
        int add = (tid >= off) ? scan[tid - off] : 0;
        __syncthreads();
        scan[tid] += add;
        __syncthreads();
    }
    const int tot = scan[255];
    int o = scan[tid] - local;
    if (isQ) {
        if (tid == 0) g_qcnt[b] = tot;
#pragma unroll
        for (int k = 0; k < 8; k++) {
            int j = tid * 8 + k;
            if (flags[k]) { g_qidx[b * NN + o] = j; g_qpos[b * NN + j] = o; o++; }
            else g_qpos[b * NN + j] = -1;
        }
        for (int i = tot + tid; i < NN; i += 256) g_qidx[b * NN + i] = 0;
    } else {
        if (tid == 0) g_cnt[b] = tot;
#pragma unroll
        for (int k = 0; k < 8; k++) {
            if (flags[k]) g_idx[b * NN + (o++)] = tid * 8 + k;
        }
        for (int i = tot + tid; i < NN; i += 256) g_idx[b * NN + i] = 0;
    }
}

// ---------------- partial sums of x rows: grid (DIM/64, BB, 8) --------------
__global__ void meanx_part(const float* __restrict__ x)
{
    const int b = blockIdx.y;
    const int z = blockIdx.z;
    const int d = blockIdx.x * 64 + threadIdx.x;
    const int yg = threadIdx.y;
    float s = 0.0f;
    const int r0 = z * 256;
    for (int j = yg; j < 256; j += 8)
        s += x[((size_t)(b * NN + r0 + j)) * DIM + d];
    __shared__ float red[8][64];
    red[yg][threadIdx.x] = s;
    __syncthreads();
    if (yg == 0) {
        float tot = 0.0f;
#pragma unroll
        for (int i = 0; i < 8; i++) tot += red[i][threadIdx.x];
        g_xpart[(b * 8 + z) * DIM + d] = tot;
    }
}

// ---------------- vmean partials: grid (INNER/64, BB, 8 d-chunks) -----------
__global__ void vmean_part(const float* __restrict__ Wqkv)
{
    const int b = blockIdx.y;
    const int z = blockIdx.z;
    const int col = blockIdx.x * 64 + threadIdx.x;
    const int yg = threadIdx.y;
    const int tid = yg * 64 + threadIdx.x;
    __shared__ float xm[64];
    if (tid < 64) {
        float s = 0.0f;
#pragma unroll
        for (int zz = 0; zz < 8; zz++) s += g_xpart[(b * 8 + zz) * DIM + z * 64 + tid];
        xm[tid] = s * (1.0f / NN);
    }
    __syncthreads();
    float s = 0.0f;
#pragma unroll
    for (int j = yg; j < 64; j += 8)
        s += xm[j] * Wqkv[(size_t)(z * 64 + j) * QKV3 + 2 * INNER + col];
    __shared__ float red[8][64];
    red[yg][threadIdx.x] = s;
    __syncthreads();
    if (yg == 0) {
        float tot = 0.0f;
#pragma unroll
        for (int i = 0; i < 8; i++) tot += red[i][threadIdx.x];
        g_vmpart[(b * 8 + z) * INNER + col] = tot;
    }
}

// ---------------- fused vmean combine + dead vector; grid (DIM/64, BB) ------
__global__ void deadvec_fused(const float* __restrict__ Wout,
                              const float* __restrict__ bias)
{
    const int b = blockIdx.y;
    const int col = blockIdx.x * 64 + threadIdx.x;
    const int yg = threadIdx.y;
    const int tid = yg * 64 + threadIdx.x;
    __shared__ float vm[INNER];
    if (tid < INNER) {
        float s = 0.0f;
#pragma unroll
        for (int z = 0; z < 8; z++) s += g_vmpart[(b * 8 + z) * INNER + tid];
        vm[tid] = s;
        if (blockIdx.x == 0) g_vmean[b * INNER + tid] = s;
    }
    __syncthreads();
    float s = 0.0f;
#pragma unroll 4
    for (int d = yg; d < INNER; d += 16)
        s += vm[d] * Wout[(size_t)d * DIM + col];
    __shared__ float red[16][64];
    red[yg][threadIdx.x] = s;
    __syncthreads();
    if (yg == 0) {
        float tot = bias[col];
#pragma unroll
        for (int i = 0; i < 16; i++) tot += red[i][threadIdx.x];
        g_dead[b * DIM + col] = tot;
    }
}

// ---------------- cnt==0 fallback: fill compacted att rows with vmean -------
__global__ void atc_vmean_fill()
{
    const int b = blockIdx.y;
    if (g_cnt[b] != 0) return;
    const int qcnt = g_qcnt[b];
    const int qpad = (qcnt + 127) & ~127;
    const int i = blockIdx.x;
    if (i >= qpad) return;
    const int tid = threadIdx.x;            // 128 thr x 4 elems
    const size_t base = ((size_t)(b * NN + i)) * INNER + tid * 4;
    bf16 h0, l0, h1, l1, h2, l2, h3, l3;
    split1(g_vmean[b * INNER + tid * 4 + 0], h0, l0);
    split1(g_vmean[b * INNER + tid * 4 + 1], h1, l1);
    split1(g_vmean[b * INNER + tid * 4 + 2], h2, l2);
    split1(g_vmean[b * INNER + tid * 4 + 3], h3, l3);
    *reinterpret_cast<unsigned*>(&g_atc_h[base])     = pack2(h0, h1);
    *reinterpret_cast<unsigned*>(&g_atc_h[base + 2]) = pack2(h2, h3);
    *reinterpret_cast<unsigned*>(&g_atc_l[base])     = pack2(l0, l1);
    *reinterpret_cast<unsigned*>(&g_atc_l[base + 2]) = pack2(l2, l3);
}

// ---------------- fill dead output rows -------------------------------------
__global__ void dead_fill(float* __restrict__ out)
{
    const int b = blockIdx.y;
    const int i = blockIdx.x;
    if (g_qpos[b * NN + i] >= 0) return;
    const int tid = threadIdx.x;
    *reinterpret_cast<float4*>(&out[((size_t)(b * NN + i)) * DIM + tid * 4]) =
        *reinterpret_cast<const float4*>(&g_dead[b * DIM + tid * 4]);
}

// ---------------------------------------------------------------------------
// bf16x3 GEMM body, 128x128 block, BK=32, 512 thr (16 warps; warp tile 32x32).
// ---------------------------------------------------------------------------
#define GALD 40
#define GBLD 136
#define G_SA(buf,hl) (sm + ((buf)*2 + (hl)) * (128*GALD))
#define G_SB(buf,hl) (sm + 4*128*GALD + ((buf)*2 + (hl)) * (32*GBLD))
#define GEMM_SMEM_BYTES ((4*128*GALD + 4*32*GBLD) * 2)

__device__ __forceinline__ void gemm_body(bf16* sm, int bm, int bn,
                                          const bf16* __restrict__ Ah,
                                          const bf16* __restrict__ Al,
                                          int lda,
                                          const int* __restrict__ ridx,
                                          const int* __restrict__ cntp,
                                          const bf16* __restrict__ Bh,
                                          const bf16* __restrict__ Bl,
                                          int ldb,
                                          const float* __restrict__ bias,
                                          float* __restrict__ outf,
                                          bf16* __restrict__ outh,
                                          bf16* __restrict__ outl,
                                          int ldo,
                                          const int* __restrict__ oidx,
                                          int K, int mode)
{
    const int b  = bm >> 11;                 // NN = 2048
    const int lm = bm & (NN - 1);
    const int bbase = b * NN;

    int cntv = NN;
    if (cntp) {
        cntv = cntp[b];
        if (lm >= ((cntv + 127) & ~127)) return;
    }

    const int tid = threadIdx.x;
    const int warp = tid >> 5;
    const int lane = tid & 31;
    const int g = lane >> 2;
    const int t = lane & 3;
    const int rowbase = (warp & 3) * 32;
    const int colbase = (warp >> 2) * 32;

    float acc[2][4][4];
#pragma unroll
    for (int mt = 0; mt < 2; mt++)
#pragma unroll
        for (int nt = 0; nt < 4; nt++)
#pragma unroll
            for (int i = 0; i < 4; i++) acc[mt][nt][i] = 0.0f;

    const int tile = lane >> 3;
    const int trow = lane & 7;

    const int arow = tid >> 2;
    const int akch = (tid & 3) * 8;
    int agrow;
    if (ridx) agrow = bbase + ridx[bbase + lm + arow];
    else      agrow = bm + arow;

    auto prefetch = [&](int buf, int k0) {
        {
            size_t go = (size_t)agrow * lda + k0 + akch;
            cp16(&G_SA(buf, 0)[arow * GALD + akch], &Ah[go]);
            cp16(&G_SA(buf, 1)[arow * GALD + akch], &Al[go]);
        }
        {
            int kr = tid >> 4, nch = (tid & 15) * 8;
            size_t go = (size_t)(k0 + kr) * ldb + bn + nch;
            cp16(&G_SB(buf, 0)[kr * GBLD + nch], &Bh[go]);
            cp16(&G_SB(buf, 1)[kr * GBLD + nch], &Bl[go]);
        }
    };

    prefetch(0, 0);
    cp_commit();

    const int NIT = K / 32;
    int buf = 0;
    for (int it = 0; it < NIT; it++) {
        if (it + 1 < NIT) { prefetch(buf ^ 1, (it + 1) * 32); cp_commit(); cp_wait<1>(); }
        else cp_wait<0>();
        __syncthreads();

        const bf16* As_h = G_SA(buf, 0);
        const bf16* As_l = G_SA(buf, 1);
        const bf16* Bs_h = G_SB(buf, 0);
        const bf16* Bs_l = G_SB(buf, 1);

#pragma unroll
        for (int kc = 0; kc < 2; kc++) {
            unsigned ah[2][4], al[2][4];
            const int amrow = (tile & 1) * 8 + trow;
            const int akoff = kc * 16 + (tile >> 1) * 8;
#pragma unroll
            for (int mt = 0; mt < 2; mt++) {
                ldsm4(ah[mt], &As_h[(rowbase + mt * 16 + amrow) * GALD + akoff]);
                ldsm4(al[mt], &As_l[(rowbase + mt * 16 + amrow) * GALD + akoff]);
            }
            const int bkrow = kc * 16 + (tile & 1) * 8 + trow;
            unsigned bh[2][4], bl[2][4];
#pragma unroll
            for (int ntp = 0; ntp < 2; ntp++) {
                const int bncol = colbase + ntp * 16 + (tile >> 1) * 8;
                ldsm4t(bh[ntp], &Bs_h[bkrow * GBLD + bncol]);
                ldsm4t(bl[ntp], &Bs_l[bkrow * GBLD + bncol]);
            }
#pragma unroll
            for (int mt = 0; mt < 2; mt++)
#pragma unroll
                for (int ntp = 0; ntp < 2; ntp++)
#pragma unroll
                    for (int q = 0; q < 2; q++)
                        mma_bf16(acc[mt][ntp * 2 + q], ah[mt], bh[ntp][q * 2], bh[ntp][q * 2 + 1]);
#pragma unroll
            for (int mt = 0; mt < 2; mt++)
#pragma unroll
                for (int ntp = 0; ntp < 2; ntp++)
#pragma unroll
                    for (int q = 0; q < 2; q++)
                        mma_bf16(acc[mt][ntp * 2 + q], ah[mt], bl[ntp][q * 2], bl[ntp][q * 2 + 1]);
#pragma unroll
            for (int mt = 0; mt < 2; mt++)
#pragma unroll
                for (int ntp = 0; ntp < 2; ntp++)
#pragma unroll
                    for (int q = 0; q < 2; q++)
                        mma_bf16(acc[mt][ntp * 2 + q], al[mt], bh[ntp][q * 2], bh[ntp][q * 2 + 1]);
        }
        __syncthreads();
        buf ^= 1;
    }

#pragma unroll
    for (int mt = 0; mt < 2; mt++) {
        const int lr0 = lm + rowbase + mt * 16 + g;
        const int lr1 = lr0 + 8;
#pragma unroll
        for (int nt = 0; nt < 4; nt++) {
            const int c0 = bn + colbase + nt * 8 + 2 * t;
            float v0 = acc[mt][nt][0], v1 = acc[mt][nt][1];
            float v2 = acc[mt][nt][2], v3 = acc[mt][nt][3];
            if (mode == 0) {
                float b0 = bias[c0], b1 = bias[c0 + 1];
                if (lr0 < cntv) {
                    int orow = bbase + oidx[bbase + lr0];
                    *reinterpret_cast<float2*>(&outf[(size_t)orow * ldo + c0]) =
                        make_float2(v0 + b0, v1 + b1);
                }
                if (lr1 < cntv) {
                    int orow = bbase + oidx[bbase + lr1];
                    *reinterpret_cast<float2*>(&outf[(size_t)orow * ldo + c0]) =
                        make_float2(v2 + b0, v3 + b1);
                }
            } else {
                bf16 h0, l0, h1, l1, h2, l2, h3, l3;
                split1(v0, h0, l0); split1(v1, h1, l1);
                split1(v2, h2, l2); split1(v3, h3, l3);
                const size_t r0o = (size_t)(bbase + lr0) * ldo + c0;
                const size_t r1o = (size_t)(bbase + lr1) * ldo + c0;
                *reinterpret_cast<unsigned*>(&outh[r0o]) = pack2(h0, h1);
                *reinterpret_cast<unsigned*>(&outl[r0o]) = pack2(l0, l1);
                *reinterpret_cast<unsigned*>(&outh[r1o]) = pack2(h2, h3);
                *reinterpret_cast<unsigned*>(&outl[r1o]) = pack2(l2, l3);
            }
        }
    }
}

// ---- fused projection GEMM: x<4 -> Q (alive rows), x>=4 -> K|V (key rows) --
__global__ __launch_bounds__(512, 1) void gemm_proj()
{
    extern __shared__ bf16 sm[];
    const int bm = blockIdx.y * 128;
    if (blockIdx.x < 4) {
        gemm_body(sm, bm, blockIdx.x * 128,
                  g_x_h, g_x_l, DIM, g_qidx, g_qcnt,
                  g_wqkv_h, g_wqkv_l, QKV3, nullptr,
                  nullptr, g_qc_h, g_qc_l, INNER, nullptr, DIM, 1);
    } else {
        gemm_body(sm, bm, (blockIdx.x - 4) * 128,
                  g_x_h, g_x_l, DIM, g_idx, g_cnt,
                  g_wqkv_h + INNER, g_wqkv_l + INNER, QKV3, nullptr,
                  nullptr, g_kvc_h, g_kvc_l, 1024, nullptr, DIM, 1);
    }
}

// ---- output GEMM: compacted att rows @ W_out + bias, scatter rows ----------
__global__ __launch_bounds__(512, 1) void gemm_out(const float* __restrict__ bias,
                                                   float* __restrict__ out)
{
    extern __shared__ bf16 sm[];
    gemm_body(sm, blockIdx.y * 128, blockIdx.x * 128,
              g_atc_h, g_atc_l, INNER, nullptr, g_qcnt,
              g_wout_h, g_wout_l, DIM, bias,
              out, nullptr, nullptr, DIM, g_qidx, INNER, 0);
}

// ---------------------------------------------------------------------------
// Attention over compacted Q rows and fused K|V buffer.
// 256 thr (8 warps), 128 q-rows/block, 64-key tiles. Q frags in registers.
// ---------------------------------------------------------------------------
#define ASLD 72
#define A_Q(hl)     (sm + (hl) * (128 * ASLD))
#define A_KV(buf,m) (sm + 2 * 128 * ASLD + ((buf) * 4 + (m)) * (64 * ASLD))
#define ATT_BF16_TOT (2 * 128 * ASLD + 8 * 64 * ASLD)
#define ATT_SMEM_BYTES (ATT_BF16_TOT * 2)

__global__ __launch_bounds__(256, 1) void attn_mma()
{
    extern __shared__ char smraw[];
    bf16* sm = reinterpret_cast<bf16*>(smraw);

    const int b  = blockIdx.y >> 3;
    const int h  = blockIdx.y & 7;
    const int q0 = blockIdx.x * 128;

    const int cnt = g_cnt[b];
    if (cnt == 0) return;                       // handled by atc_vmean_fill

    const int qcnt = g_qcnt[b];
    const int qpad = (qcnt + 127) & ~127;
    if (q0 >= qpad) return;

    const int ntiles = (cnt + 63) >> 6;

    const int tid = threadIdx.x;
    const int warp = tid >> 5;
    const int lane = tid & 31;
    const int g = lane >> 2;
    const int t = lane & 3;
    const int rb = warp * 16;
    const float scale = 0.125f;
    const int tile = lane >> 3;
    const int trow = lane & 7;

#pragma unroll
    for (int j = 0; j < 4; j++) {
        int c = tid * 4 + j;
        int row = c >> 3, dch = (c & 7) * 8;
        size_t base = (size_t)(b * NN + q0 + row) * INNER + h * 64 + dch;
        cp16(&A_Q(0)[row * ASLD + dch], &g_qc_h[base]);
        cp16(&A_Q(1)[row * ASLD + dch], &g_qc_l[base]);
    }
    cp_commit();

    auto pref = [&](int buf, int kt0) {
#pragma unroll
        for (int j = 0; j < 2; j++) {
            int c = tid * 2 + j;
            int row = c >> 3, dch = (c & 7) * 8;
            size_t base = ((size_t)(b * NN + kt0 + row)) * 1024 + h * 64 + dch;
            cp16(&A_KV(buf, 0)[row * ASLD + dch], &g_kvc_h[base]);
            cp16(&A_KV(buf, 1)[row * ASLD + dch], &g_kvc_l[base]);
            cp16(&A_KV(buf, 2)[row * ASLD + dch], &g_kvc_h[base + 512]);
            cp16(&A_KV(buf, 3)[row * ASLD + dch], &g_kvc_l[base + 512]);
        }
    };

    pref(0, 0);
    cp_commit();

    float O[8][4];
#pragma unroll
    for (int nt = 0; nt < 8; nt++)
#pragma unroll
        for (int i = 0; i < 4; i++) O[nt][i] = 0.0f;
    float lsum0 = 0.0f, lsum8 = 0.0f;

    unsigned aqh[4][4], aql[4][4];
    bool qloaded = false;
    const int qr = rb + (tile & 1) * 8 + trow;

    int buf = 0;
    for (int kt = 0; kt < ntiles; kt++) {
        const int kt0 = kt * 64;
        if (kt + 1 < ntiles) { pref(buf ^ 1, (kt + 1) * 64); cp_commit(); cp_wait<1>(); }
        else cp_wait<0>();
        __syncthreads();

        if (!qloaded) {
            qloaded = true;
#pragma unroll
            for (int kc = 0; kc < 4; kc++) {
                ldsm4(aqh[kc], &A_Q(0)[qr * ASLD + kc * 16 + (tile >> 1) * 8]);
                ldsm4(aql[kc], &A_Q(1)[qr * ASLD + kc * 16 + (tile >> 1) * 8]);
            }
        }

        const bf16* KHs = A_KV(buf, 0);
        const bf16* KLs = A_KV(buf, 1);
        const bf16* VHs = A_KV(buf, 2);
        const bf16* VLs = A_KV(buf, 3);

        unsigned pah[4][4], pal[4][4];

#pragma unroll
        for (int half = 0; half < 2; half++) {
            float sc[4][4];
#pragma unroll
            for (int nt = 0; nt < 4; nt++)
#pragma unroll
                for (int i = 0; i < 4; i++) sc[nt][i] = 0.0f;

#pragma unroll
            for (int kc = 0; kc < 4; kc++) {
                const int koff = kc * 16 + (tile & 1) * 8;
                unsigned kbh[2][4], kbl[2][4];
#pragma unroll
                for (int ntp = 0; ntp < 2; ntp++) {
                    const int nrow = (half * 2 + ntp) * 16 + (tile >> 1) * 8 + trow;
                    ldsm4(kbh[ntp], &KHs[nrow * ASLD + koff]);
                    ldsm4(kbl[ntp], &KLs[nrow * ASLD + koff]);
                }
#pragma unroll
                for (int ntp = 0; ntp < 2; ntp++)
#pragma unroll
                    for (int q = 0; q < 2; q++)
                        mma_bf16(sc[ntp * 2 + q], aqh[kc], kbh[ntp][q * 2], kbh[ntp][q * 2 + 1]);
#pragma unroll
                for (int ntp = 0; ntp < 2; ntp++)
#pragma unroll
                    for (int q = 0; q < 2; q++)
                        mma_bf16(sc[ntp * 2 + q], aqh[kc], kbl[ntp][q * 2], kbl[ntp][q * 2 + 1]);
#pragma unroll
                for (int ntp = 0; ntp < 2; ntp++)
#pragma unroll
                    for (int q = 0; q < 2; q++)
                        mma_bf16(sc[ntp * 2 + q], aql[kc], kbh[ntp][q * 2], kbh[ntp][q * 2 + 1]);
            }

#pragma unroll
            for (int ntl = 0; ntl < 4; ntl++) {
                const int nt = half * 4 + ntl;
                const int kch = nt >> 1, q = nt & 1;
                const int colg = kt0 + nt * 8 + 2 * t;
                const bool v0c = colg < cnt;
                const bool v1c = colg + 1 < cnt;
                float p0 = v0c ? __expf(sc[ntl][0] * scale) : 0.0f;
                float p1 = v1c ? __expf(sc[ntl][1] * scale) : 0.0f;
                float p2 = v0c ? __expf(sc[ntl][2] * scale) : 0.0f;
                float p3 = v1c ? __expf(sc[ntl][3] * scale) : 0.0f;
                lsum0 += p0 + p1;
                lsum8 += p2 + p3;
                bf16 h0, l0, h1, l1, h2, l2, h3, l3;
                split1(p0, h0, l0); split1(p1, h1, l1);
                split1(p2, h2, l2); split1(p3, h3, l3);
                pah[kch][q * 2 + 0] = pack2(h0, h1);
                pah[kch][q * 2 + 1] = pack2(h2, h3);
                pal[kch][q * 2 + 0] = pack2(l0, l1);
                pal[kch][q * 2 + 1] = pack2(l2, l3);
            }
        }

#pragma unroll
        for (int kch = 0; kch < 4; kch++) {
            const int keyrow = kch * 16 + (tile & 1) * 8 + trow;
            unsigned vh[4][4], vl[4][4];
#pragma unroll
            for (int dp = 0; dp < 4; dp++) {
                const int dcol = dp * 16 + (tile >> 1) * 8;
                ldsm4t(vh[dp], &VHs[keyrow * ASLD + dcol]);
                ldsm4t(vl[dp], &VLs[keyrow * ASLD + dcol]);
            }
#pragma unroll
            for (int dp = 0; dp < 4; dp++)
#pragma unroll
                for (int q = 0; q < 2; q++)
                    mma_bf16(O[dp * 2 + q], pah[kch], vh[dp][q * 2], vh[dp][q * 2 + 1]);
#pragma unroll
            for (int dp = 0; dp < 4; dp++)
#pragma unroll
                for (int q = 0; q < 2; q++)
                    mma_bf16(O[dp * 2 + q], pah[kch], vl[dp][q * 2], vl[dp][q * 2 + 1]);
#pragma unroll
            for (int dp = 0; dp < 4; dp++)
#pragma unroll
                for (int q = 0; q < 2; q++)
                    mma_bf16(O[dp * 2 + q], pal[kch], vh[dp][q * 2], vh[dp][q * 2 + 1]);
        }
        __syncthreads();
        buf ^= 1;
    }

    lsum0 += __shfl_xor_sync(0xffffffffu, lsum0, 1);
    lsum0 += __shfl_xor_sync(0xffffffffu, lsum0, 2);
    lsum8 += __shfl_xor_sync(0xffffffffu, lsum8, 1);
    lsum8 += __shfl_xor_sync(0xffffffffu, lsum8, 2);
    const float inv0 = 1.0f / lsum0;
    const float inv8 = 1.0f / lsum8;

    const size_t row0 = (size_t)(b * NN + q0 + rb + g);
    const size_t row8 = row0 + 8;
#pragma unroll
    for (int nt = 0; nt < 8; nt++) {
        const int d = h * 64 + nt * 8 + 2 * t;
        float v0 = O[nt][0] * inv0, v1 = O[nt][1] * inv0;
        float v2 = O[nt][2] * inv8, v3 = O[nt][3] * inv8;
        bf16 h0, l0, h1, l1, h2, l2, h3, l3;
        split1(v0, h0, l0); split1(v1, h1, l1);
        split1(v2, h2, l2); split1(v3, h3, l3);
        *reinterpret_cast<unsigned*>(&g_atc_h[row0 * INNER + d]) = pack2(h0, h1);
        *reinterpret_cast<unsigned*>(&g_atc_l[row0 * INNER + d]) = pack2(l0, l1);
        *reinterpret_cast<unsigned*>(&g_atc_h[row8 * INNER + d]) = pack2(h2, h3);
        *reinterpret_cast<unsigned*>(&g_atc_l[row8 * INNER + d]) = pack2(l2, l3);
    }
}

// ---------------------------------------------------------------------------
extern "C" void kernel_launch(void* const* d_in, const int* in_sizes, int n_in,
                              void* d_out, int out_size)
{
    const float* x     = (const float*)d_in[0];
    const int*   mnp   = (const int*)d_in[1];
    const int*   mbert = (const int*)d_in[2];
    const float* Wqkv  = (const float*)d_in[3];
    const float* Wout  = (const float*)d_in[4];
    const float* bout  = (const float*)d_in[5];
    float* out = (float*)d_out;

    cudaFuncSetAttribute(gemm_proj, cudaFuncAttributeMaxDynamicSharedMemorySize,
                         GEMM_SMEM_BYTES);
    cudaFuncSetAttribute(gemm_out, cudaFuncAttributeMaxDynamicSharedMemorySize,
                         GEMM_SMEM_BYTES);
    cudaFuncSetAttribute(attn_mma, cudaFuncAttributeMaxDynamicSharedMemorySize,
                         ATT_SMEM_BYTES);

    cudaStream_t s2;
    cudaStreamCreateWithFlags(&s2, cudaStreamNonBlocking);
    cudaEvent_t e0, e_bb, e_wout, e_df;
    cudaEventCreateWithFlags(&e0,     cudaEventDisableTiming);
    cudaEventCreateWithFlags(&e_bb,   cudaEventDisableTiming);
    cudaEventCreateWithFlags(&e_wout, cudaEventDisableTiming);
    cudaEventCreateWithFlags(&e_df,   cudaEventDisableTiming);

    // fork
    cudaEventRecord(e0, 0);
    cudaStreamWaitEvent(s2, e0, 0);

    // main stream: split x+Wqkv (vectorized)
    split_xw<<<1024, 256>>>(x, Wqkv);

    // side stream: compactions + mean chain + cnt==0 fixup + Wout split + dead fill
    build_both<<<dim3(2, BB), 256, 0, s2>>>(mnp, mbert);
    cudaEventRecord(e_bb, s2);
    meanx_part<<<dim3(DIM / 64, BB, 8), dim3(64, 8), 0, s2>>>(x);
    vmean_part<<<dim3(INNER / 64, BB, 8), dim3(64, 8), 0, s2>>>(Wqkv);
    deadvec_fused<<<dim3(DIM / 64, BB), dim3(64, 16), 0, s2>>>(Wout, bout);
    atc_vmean_fill<<<dim3(NN, BB), 128, 0, s2>>>();
    split_wout<<<128, 256, 0, s2>>>(Wout);
    cudaEventRecord(e_wout, s2);
    dead_fill<<<dim3(NN, BB), 128, 0, s2>>>(out);
    cudaEventRecord(e_df, s2);

    // main stream: projections (needs compaction indices only)
    cudaStreamWaitEvent(0, e_bb, 0);
    gemm_proj<<<dim3(12, MROWS / 128), 512, GEMM_SMEM_BYTES>>>();

    // attention (no mean-chain dependency; cnt==0 covered by atc_vmean_fill)
    attn_mma<<<dim3(NN / 128, BB * HH), 256, ATT_SMEM_BYTES>>>();

    // output projection (needs Wout split + cnt==0 fixup, both before e_wout)
    cudaStreamWaitEvent(0, e_wout, 0);
    gemm_out<<<dim3(DIM / 128, MROWS / 128), 512, GEMM_SMEM_BYTES>>>(bout, out);

    // join
    cudaStreamWaitEvent(0, e_df, 0);
}

// round 17
// speedup vs baseline: 1.1728x; 1.1210x over previous
#include <cuda_runtime.h>
#include <cuda_bf16.h>
#include <math.h>

#define BB    2
#define NN    2048
#define DIM   512
#define HH    8
#define DH    64
#define INNER 512
#define QKV3  1536
#define MROWS (BB*NN)      // 4096

typedef __nv_bfloat16 bf16;

// ---------------- device scratch (no allocation allowed) ----------------
__device__ bf16 g_x_h[MROWS * DIM],    g_x_l[MROWS * DIM];
__device__ bf16 g_wqkv_h[DIM * QKV3],  g_wqkv_l[DIM * QKV3];
__device__ bf16 g_wout_h[INNER * DIM], g_wout_l[INNER * DIM];

// key compaction + fused K|V buffer (K at col 0..511, V at col 512..1023)
__device__ int  g_cnt[BB];
__device__ int  g_idx[BB * NN];
__device__ bf16 g_kvc_h[BB * NN * 1024], g_kvc_l[BB * NN * 1024];
__device__ float g_xpart[BB * 8 * DIM];
__device__ float g_vmpart[BB * 8 * INNER];
__device__ float g_vmean[BB * INNER];
__device__ float g_dead[BB * DIM];

// query compaction
__device__ int  g_qcnt[BB];
__device__ int  g_qidx[BB * NN];
__device__ int  g_qpos[BB * NN];
__device__ bf16 g_qc_h[BB * NN * INNER], g_qc_l[BB * NN * INNER];
__device__ bf16 g_atc_h[BB * NN * INNER], g_atc_l[BB * NN * INNER];

// ---------------- helpers ----------------
__device__ __forceinline__ unsigned s2u(const void* p) {
    return (unsigned)__cvta_generic_to_shared(p);
}
__device__ __forceinline__ void ldsm4(unsigned* r, const void* p) {
    asm volatile("ldmatrix.sync.aligned.m8n8.x4.shared.b16 {%0,%1,%2,%3}, [%4];"
        : "=r"(r[0]), "=r"(r[1]), "=r"(r[2]), "=r"(r[3]) : "r"(s2u(p)));
}
__device__ __forceinline__ void ldsm4t(unsigned* r, const void* p) {
    asm volatile("ldmatrix.sync.aligned.m8n8.x4.trans.shared.b16 {%0,%1,%2,%3}, [%4];"
        : "=r"(r[0]), "=r"(r[1]), "=r"(r[2]), "=r"(r[3]) : "r"(s2u(p)));
}
__device__ __forceinline__ void cp16(void* s, const void* g) {
    asm volatile("cp.async.cg.shared.global [%0], [%1], 16;" :: "r"(s2u(s)), "l"(g));
}
__device__ __forceinline__ void cp_commit() { asm volatile("cp.async.commit_group;"); }
template<int N> __device__ __forceinline__ void cp_wait() {
    asm volatile("cp.async.wait_group %0;" :: "n"(N));
}
__device__ __forceinline__ void mma_bf16(float* c, const unsigned* a, unsigned b0, unsigned b1) {
    asm volatile(
        "mma.sync.aligned.m16n8k16.row.col.f32.bf16.bf16.f32 "
        "{%0,%1,%2,%3}, {%4,%5,%6,%7}, {%8,%9}, {%0,%1,%2,%3};"
        : "+f"(c[0]), "+f"(c[1]), "+f"(c[2]), "+f"(c[3])
        : "r"(a[0]), "r"(a[1]), "r"(a[2]), "r"(a[3]), "r"(b0), "r"(b1));
}
__device__ __forceinline__ unsigned pack2(bf16 a, bf16 b) {
    __nv_bfloat162 v; v.x = a; v.y = b;
    return *reinterpret_cast<unsigned*>(&v);
}
__device__ __forceinline__ void split1(float v, bf16& h, bf16& l) {
    h = __float2bfloat16(v);
    l = __float2bfloat16(v - __bfloat162float(h));
}
__device__ __forceinline__ void split4(const float4 v, uint2& ho, uint2& lo) {
    bf16 h0, l0, h1, l1, h2, l2, h3, l3;
    split1(v.x, h0, l0); split1(v.y, h1, l1);
    split1(v.z, h2, l2); split1(v.w, h3, l3);
    ho.x = pack2(h0, h1); ho.y = pack2(h2, h3);
    lo.x = pack2(l0, l1); lo.y = pack2(l2, l3);
}

// ---------------- prep: vectorized splits ----------------
__global__ void split_xw(const float* __restrict__ x, const float* __restrict__ wqkv)
{
    const int n1 = (MROWS * DIM) / 4, n2 = (DIM * QKV3) / 4;
    const int total = n1 + n2;
    for (int i = blockIdx.x * blockDim.x + threadIdx.x; i < total;
         i += gridDim.x * blockDim.x) {
        float4 v; bf16 *hi, *lo; int off;
        if (i < n1) { off = i * 4; v = *reinterpret_cast<const float4*>(&x[off]);
                      hi = g_x_h; lo = g_x_l; }
        else        { off = (i - n1) * 4; v = *reinterpret_cast<const float4*>(&wqkv[off]);
                      hi = g_wqkv_h; lo = g_wqkv_l; }
        uint2 ho, lw; split4(v, ho, lw);
        *reinterpret_cast<uint2*>(&hi[off]) = ho;
        *reinterpret_cast<uint2*>(&lo[off]) = lw;
    }
}
__global__ void split_wout(const float* __restrict__ wout)
{
    const int total = (INNER * DIM) / 4;
    for (int i = blockIdx.x * blockDim.x + threadIdx.x; i < total;
         i += gridDim.x * blockDim.x) {
        int off = i * 4;
        float4 v = *reinterpret_cast<const float4*>(&wout[off]);
        uint2 ho, lw; split4(v, ho, lw);
        *reinterpret_cast<uint2*>(&g_wout_h[off]) = ho;
        *reinterpret_cast<uint2*>(&g_wout_l[off]) = lw;
    }
}

// ---------------- fused compactions (parallel scan); grid (2, BB) -----------
__global__ void build_both(const int* __restrict__ mnp, const int* __restrict__ mbert)
{
    const int b = blockIdx.y;
    const bool isQ = (blockIdx.x == 1);
    const int tid = threadIdx.x;
    __shared__ int scan[256];

    int flags[8];
    int local = 0;
#pragma unroll
    for (int k = 0; k < 8; k++) {
        int j = tid * 8 + k;
        int f;
        if (isQ) f = (mnp[b * NN + j] == 1);
        else     f = (mnp[b * NN + j] == 1) && (mbert[b * NN + j] == 0);
        flags[k] = f; local += f;
    }
    scan[tid] = local;
    __syncthreads();
#pragma unroll
    for (int off = 1; off < 256; off <<= 1) {
        int add = (tid >= off) ? scan[tid - off] : 0;
        __syncthreads();
        scan[tid] += add;
        __syncthreads();
    }
    const int tot = scan[255];
    int o = scan[tid] - local;
    if (isQ) {
        if (tid == 0) g_qcnt[b] = tot;
#pragma unroll
        for (int k = 0; k < 8; k++) {
            int j = tid * 8 + k;
            if (flags[k]) { g_qidx[b * NN + o] = j; g_qpos[b * NN + j] = o; o++; }
            else g_qpos[b * NN + j] = -1;
        }
        for (int i = tot + tid; i < NN; i += 256) g_qidx[b * NN + i] = 0;
    } else {
        if (tid == 0) g_cnt[b] = tot;
#pragma unroll
        for (int k = 0; k < 8; k++) {
            if (flags[k]) g_idx[b * NN + (o++)] = tid * 8 + k;
        }
        for (int i = tot + tid; i < NN; i += 256) g_idx[b * NN + i] = 0;
    }
}

// ---------------- partial sums of x rows: grid (DIM/64, BB, 8) --------------
__global__ void meanx_part(const float* __restrict__ x)
{
    const int b = blockIdx.y;
    const int z = blockIdx.z;
    const int d = blockIdx.x * 64 + threadIdx.x;
    const int yg = threadIdx.y;
    float s = 0.0f;
    const int r0 = z * 256;
    for (int j = yg; j < 256; j += 8)
        s += x[((size_t)(b * NN + r0 + j)) * DIM + d];
    __shared__ float red[8][64];
    red[yg][threadIdx.x] = s;
    __syncthreads();
    if (yg == 0) {
        float tot = 0.0f;
#pragma unroll
        for (int i = 0; i < 8; i++) tot += red[i][threadIdx.x];
        g_xpart[(b * 8 + z) * DIM + d] = tot;
    }
}

// ---------------- vmean partials: grid (INNER/64, BB, 8 d-chunks) -----------
__global__ void vmean_part(const float* __restrict__ Wqkv)
{
    const int b = blockIdx.y;
    const int z = blockIdx.z;
    const int col = blockIdx.x * 64 + threadIdx.x;
    const int yg = threadIdx.y;
    const int tid = yg * 64 + threadIdx.x;
    __shared__ float xm[64];
    if (tid < 64) {
        float s = 0.0f;
#pragma unroll
        for (int zz = 0; zz < 8; zz++) s += g_xpart[(b * 8 + zz) * DIM + z * 64 + tid];
        xm[tid] = s * (1.0f / NN);
    }
    __syncthreads();
    float s = 0.0f;
#pragma unroll
    for (int j = yg; j < 64; j += 8)
        s += xm[j] * Wqkv[(size_t)(z * 64 + j) * QKV3 + 2 * INNER + col];
    __shared__ float red[8][64];
    red[yg][threadIdx.x] = s;
    __syncthreads();
    if (yg == 0) {
        float tot = 0.0f;
#pragma unroll
        for (int i = 0; i < 8; i++) tot += red[i][threadIdx.x];
        g_vmpart[(b * 8 + z) * INNER + col] = tot;
    }
}

// ---------------- fused vmean combine + dead vector; grid (DIM/64, BB) ------
__global__ void deadvec_fused(const float* __restrict__ Wout,
                              const float* __restrict__ bias)
{
    const int b = blockIdx.y;
    const int col = blockIdx.x * 64 + threadIdx.x;
    const int yg = threadIdx.y;
    const int tid = yg * 64 + threadIdx.x;
    __shared__ float vm[INNER];
    if (tid < INNER) {
        float s = 0.0f;
#pragma unroll
        for (int z = 0; z < 8; z++) s += g_vmpart[(b * 8 + z) * INNER + tid];
        vm[tid] = s;
        if (blockIdx.x == 0) g_vmean[b * INNER + tid] = s;
    }
    __syncthreads();
    float s = 0.0f;
#pragma unroll 4
    for (int d = yg; d < INNER; d += 16)
        s += vm[d] * Wout[(size_t)d * DIM + col];
    __shared__ float red[16][64];
    red[yg][threadIdx.x] = s;
    __syncthreads();
    if (yg == 0) {
        float tot = bias[col];
#pragma unroll
        for (int i = 0; i < 16; i++) tot += red[i][threadIdx.x];
        g_dead[b * DIM + col] = tot;
    }
}

// ---------------- cnt==0 fallback: fill compacted att rows with vmean -------
__global__ void atc_vmean_fill()
{
    const int b = blockIdx.y;
    if (g_cnt[b] != 0) return;
    const int qcnt = g_qcnt[b];
    const int qpad = (qcnt + 127) & ~127;
    const int i = blockIdx.x;
    if (i >= qpad) return;
    const int tid = threadIdx.x;
    const size_t base = ((size_t)(b * NN + i)) * INNER + tid * 4;
    bf16 h0, l0, h1, l1, h2, l2, h3, l3;
    split1(g_vmean[b * INNER + tid * 4 + 0], h0, l0);
    split1(g_vmean[b * INNER + tid * 4 + 1], h1, l1);
    split1(g_vmean[b * INNER + tid * 4 + 2], h2, l2);
    split1(g_vmean[b * INNER + tid * 4 + 3], h3, l3);
    *reinterpret_cast<unsigned*>(&g_atc_h[base])     = pack2(h0, h1);
    *reinterpret_cast<unsigned*>(&g_atc_h[base + 2]) = pack2(h2, h3);
    *reinterpret_cast<unsigned*>(&g_atc_l[base])     = pack2(l0, l1);
    *reinterpret_cast<unsigned*>(&g_atc_l[base + 2]) = pack2(l2, l3);
}

// ---------------- zero alive output rows (for split-K atomic accumulate) ----
__global__ void zero_alive(float* __restrict__ out)
{
    const int b = blockIdx.y;
    const int i = blockIdx.x;
    if (g_qpos[b * NN + i] < 0) return;
    const int tid = threadIdx.x;
    float4 z = make_float4(0.f, 0.f, 0.f, 0.f);
    *reinterpret_cast<float4*>(&out[((size_t)(b * NN + i)) * DIM + tid * 4]) = z;
}

// ---------------- fill dead output rows -------------------------------------
__global__ void dead_fill(float* __restrict__ out)
{
    const int b = blockIdx.y;
    const int i = blockIdx.x;
    if (g_qpos[b * NN + i] >= 0) return;
    const int tid = threadIdx.x;
    *reinterpret_cast<float4*>(&out[((size_t)(b * NN + i)) * DIM + tid * 4]) =
        *reinterpret_cast<const float4*>(&g_dead[b * DIM + tid * 4]);
}

// ---------------------------------------------------------------------------
// bf16x3 GEMM body, 128x128 block, BK=32, 512 thr (16 warps; warp tile 32x32).
// mode 1: bf16 hi/lo store. mode 2: fp32 atomicAdd into pre-zeroed rows
// (+bias when non-null), with output-row indirection.
// ---------------------------------------------------------------------------
#define GALD 40
#define GBLD 136
#define G_SA(buf,hl) (sm + ((buf)*2 + (hl)) * (128*GALD))
#define G_SB(buf,hl) (sm + 4*128*GALD + ((buf)*2 + (hl)) * (32*GBLD))
#define GEMM_SMEM_BYTES ((4*128*GALD + 4*32*GBLD) * 2)

__device__ __forceinline__ void gemm_body(bf16* sm, int bm, int bn, int kbase,
                                          const bf16* __restrict__ Ah,
                                          const bf16* __restrict__ Al,
                                          int lda,
                                          const int* __restrict__ ridx,
                                          const int* __restrict__ cntp,
                                          const bf16* __restrict__ Bh,
                                          const bf16* __restrict__ Bl,
                                          int ldb,
                                          const float* __restrict__ bias,
                                          float* __restrict__ outf,
                                          bf16* __restrict__ outh,
                                          bf16* __restrict__ outl,
                                          int ldo,
                                          const int* __restrict__ oidx,
                                          int K, int mode)
{
    const int b  = bm >> 11;                 // NN = 2048
    const int lm = bm & (NN - 1);
    const int bbase = b * NN;

    int cntv = NN;
    if (cntp) {
        cntv = cntp[b];
        if (lm >= ((cntv + 127) & ~127)) return;
    }

    const int tid = threadIdx.x;
    const int warp = tid >> 5;
    const int lane = tid & 31;
    const int g = lane >> 2;
    const int t = lane & 3;
    const int rowbase = (warp & 3) * 32;
    const int colbase = (warp >> 2) * 32;

    float acc[2][4][4];
#pragma unroll
    for (int mt = 0; mt < 2; mt++)
#pragma unroll
        for (int nt = 0; nt < 4; nt++)
#pragma unroll
            for (int i = 0; i < 4; i++) acc[mt][nt][i] = 0.0f;

    const int tile = lane >> 3;
    const int trow = lane & 7;

    const int arow = tid >> 2;
    const int akch = (tid & 3) * 8;
    int agrow;
    if (ridx) agrow = bbase + ridx[bbase + lm + arow];
    else      agrow = bm + arow;

    auto prefetch = [&](int buf, int k0) {
        {
            size_t go = (size_t)agrow * lda + kbase + k0 + akch;
            cp16(&G_SA(buf, 0)[arow * GALD + akch], &Ah[go]);
            cp16(&G_SA(buf, 1)[arow * GALD + akch], &Al[go]);
        }
        {
            int kr = tid >> 4, nch = (tid & 15) * 8;
            size_t go = (size_t)(kbase + k0 + kr) * ldb + bn + nch;
            cp16(&G_SB(buf, 0)[kr * GBLD + nch], &Bh[go]);
            cp16(&G_SB(buf, 1)[kr * GBLD + nch], &Bl[go]);
        }
    };

    prefetch(0, 0);
    cp_commit();

    const int NIT = K / 32;
    int buf = 0;
    for (int it = 0; it < NIT; it++) {
        if (it + 1 < NIT) { prefetch(buf ^ 1, (it + 1) * 32); cp_commit(); cp_wait<1>(); }
        else cp_wait<0>();
        __syncthreads();

        const bf16* As_h = G_SA(buf, 0);
        const bf16* As_l = G_SA(buf, 1);
        const bf16* Bs_h = G_SB(buf, 0);
        const bf16* Bs_l = G_SB(buf, 1);

#pragma unroll
        for (int kc = 0; kc < 2; kc++) {
            unsigned ah[2][4], al[2][4];
            const int amrow = (tile & 1) * 8 + trow;
            const int akoff = kc * 16 + (tile >> 1) * 8;
#pragma unroll
            for (int mt = 0; mt < 2; mt++) {
                ldsm4(ah[mt], &As_h[(rowbase + mt * 16 + amrow) * GALD + akoff]);
                ldsm4(al[mt], &As_l[(rowbase + mt * 16 + amrow) * GALD + akoff]);
            }
            const int bkrow = kc * 16 + (tile & 1) * 8 + trow;
            unsigned bh[2][4], bl[2][4];
#pragma unroll
            for (int ntp = 0; ntp < 2; ntp++) {
                const int bncol = colbase + ntp * 16 + (tile >> 1) * 8;
                ldsm4t(bh[ntp], &Bs_h[bkrow * GBLD + bncol]);
                ldsm4t(bl[ntp], &Bs_l[bkrow * GBLD + bncol]);
            }
#pragma unroll
            for (int mt = 0; mt < 2; mt++)
#pragma unroll
                for (int ntp = 0; ntp < 2; ntp++)
#pragma unroll
                    for (int q = 0; q < 2; q++)
                        mma_bf16(acc[mt][ntp * 2 + q], ah[mt], bh[ntp][q * 2], bh[ntp][q * 2 + 1]);
#pragma unroll
            for (int mt = 0; mt < 2; mt++)
#pragma unroll
                for (int ntp = 0; ntp < 2; ntp++)
#pragma unroll
                    for (int q = 0; q < 2; q++)
                        mma_bf16(acc[mt][ntp * 2 + q], ah[mt], bl[ntp][q * 2], bl[ntp][q * 2 + 1]);
#pragma unroll
            for (int mt = 0; mt < 2; mt++)
#pragma unroll
                for (int ntp = 0; ntp < 2; ntp++)
#pragma unroll
                    for (int q = 0; q < 2; q++)
                        mma_bf16(acc[mt][ntp * 2 + q], al[mt], bh[ntp][q * 2], bh[ntp][q * 2 + 1]);
        }
        __syncthreads();
        buf ^= 1;
    }

#pragma unroll
    for (int mt = 0; mt < 2; mt++) {
        const int lr0 = lm + rowbase + mt * 16 + g;
        const int lr1 = lr0 + 8;
#pragma unroll
        for (int nt = 0; nt < 4; nt++) {
            const int c0 = bn + colbase + nt * 8 + 2 * t;
            float v0 = acc[mt][nt][0], v1 = acc[mt][nt][1];
            float v2 = acc[mt][nt][2], v3 = acc[mt][nt][3];
            if (mode == 2) {
                float b0 = bias ? bias[c0] : 0.0f;
                float b1 = bias ? bias[c0 + 1] : 0.0f;
                if (lr0 < cntv) {
                    int orow = bbase + oidx[bbase + lr0];
                    atomicAdd(&outf[(size_t)orow * ldo + c0],     v0 + b0);
                    atomicAdd(&outf[(size_t)orow * ldo + c0 + 1], v1 + b1);
                }
                if (lr1 < cntv) {
                    int orow = bbase + oidx[bbase + lr1];
                    atomicAdd(&outf[(size_t)orow * ldo + c0],     v2 + b0);
                    atomicAdd(&outf[(size_t)orow * ldo + c0 + 1], v3 + b1);
                }
            } else {
                bf16 h0, l0, h1, l1, h2, l2, h3, l3;
                split1(v0, h0, l0); split1(v1, h1, l1);
                split1(v2, h2, l2); split1(v3, h3, l3);
                const size_t r0o = (size_t)(bbase + lr0) * ldo + c0;
                const size_t r1o = (size_t)(bbase + lr1) * ldo + c0;
                *reinterpret_cast<unsigned*>(&outh[r0o]) = pack2(h0, h1);
                *reinterpret_cast<unsigned*>(&outl[r0o]) = pack2(l0, l1);
                *reinterpret_cast<unsigned*>(&outh[r1o]) = pack2(h2, h3);
                *reinterpret_cast<unsigned*>(&outl[r1o]) = pack2(l2, l3);
            }
        }
    }
}

// ---- fused projection GEMM: x<4 -> Q (alive rows), x>=4 -> K|V (key rows) --
__global__ __launch_bounds__(512, 1) void gemm_proj()
{
    extern __shared__ bf16 sm[];
    const int bm = blockIdx.y * 128;
    if (blockIdx.x < 4) {
        gemm_body(sm, bm, blockIdx.x * 128, 0,
                  g_x_h, g_x_l, DIM, g_qidx, g_qcnt,
                  g_wqkv_h, g_wqkv_l, QKV3, nullptr,
                  nullptr, g_qc_h, g_qc_l, INNER, nullptr, DIM, 1);
    } else {
        gemm_body(sm, bm, (blockIdx.x - 4) * 128, 0,
                  g_x_h, g_x_l, DIM, g_idx, g_cnt,
                  g_wqkv_h + INNER, g_wqkv_l + INNER, QKV3, nullptr,
                  nullptr, g_kvc_h, g_kvc_l, 1024, nullptr, DIM, 1);
    }
}

// ---- output GEMM: split-K atomic accumulate into pre-zeroed alive rows -----
__global__ __launch_bounds__(512, 1) void gemm_out(const float* __restrict__ bias,
                                                   float* __restrict__ out)
{
    extern __shared__ bf16 sm[];
    const int kz = blockIdx.z;
    gemm_body(sm, blockIdx.y * 128, blockIdx.x * 128, kz * 256,
              g_atc_h, g_atc_l, INNER, nullptr, g_qcnt,
              g_wout_h, g_wout_l, DIM, (kz == 0) ? bias : nullptr,
              out, nullptr, nullptr, DIM, g_qidx, 256, 2);
}

// ---------------------------------------------------------------------------
// Attention over compacted Q rows and fused K|V buffer.
// 256 thr, 128 q-rows/block, 64-key tiles. Q frags bf16-hi only (2-pass QK).
// ---------------------------------------------------------------------------
#define ASLD 72
#define A_Q          (sm)
#define A_KV(buf,m)  (sm + 128 * ASLD + ((buf) * 4 + (m)) * (64 * ASLD))
#define ATT_BF16_TOT (128 * ASLD + 8 * 64 * ASLD)
#define ATT_SMEM_BYTES (ATT_BF16_TOT * 2)

__global__ __launch_bounds__(256, 1) void attn_mma()
{
    extern __shared__ char smraw[];
    bf16* sm = reinterpret_cast<bf16*>(smraw);

    const int b  = blockIdx.y >> 3;
    const int h  = blockIdx.y & 7;
    const int q0 = blockIdx.x * 128;

    const int cnt = g_cnt[b];
    if (cnt == 0) return;                       // handled by atc_vmean_fill

    const int qcnt = g_qcnt[b];
    const int qpad = (qcnt + 127) & ~127;
    if (q0 >= qpad) return;

    const int ntiles = (cnt + 63) >> 6;

    const int tid = threadIdx.x;
    const int warp = tid >> 5;
    const int lane = tid & 31;
    const int g = lane >> 2;
    const int t = lane & 3;
    const int rb = warp * 16;
    const float scale = 0.125f;
    const int tile = lane >> 3;
    const int trow = lane & 7;

    // Q prefetch: hi only (2-pass QK uses q at bf16 precision)
#pragma unroll
    for (int j = 0; j < 4; j++) {
        int c = tid * 4 + j;                    // 0..1023 8-elem chunks
        int row = c >> 3, dch = (c & 7) * 8;
        size_t base = (size_t)(b * NN + q0 + row) * INNER + h * 64 + dch;
        cp16(&A_Q[row * ASLD + dch], &g_qc_h[base]);
    }
    cp_commit();

    auto pref = [&](int buf, int kt0) {
#pragma unroll
        for (int j = 0; j < 2; j++) {
            int c = tid * 2 + j;
            int row = c >> 3, dch = (c & 7) * 8;
            size_t base = ((size_t)(b * NN + kt0 + row)) * 1024 + h * 64 + dch;
            cp16(&A_KV(buf, 0)[row * ASLD + dch], &g_kvc_h[base]);
            cp16(&A_KV(buf, 1)[row * ASLD + dch], &g_kvc_l[base]);
            cp16(&A_KV(buf, 2)[row * ASLD + dch], &g_kvc_h[base + 512]);
            cp16(&A_KV(buf, 3)[row * ASLD + dch], &g_kvc_l[base + 512]);
        }
    };

    pref(0, 0);
    cp_commit();

    float O[8][4];
#pragma unroll
    for (int nt = 0; nt < 8; nt++)
#pragma unroll
        for (int i = 0; i < 4; i++) O[nt][i] = 0.0f;
    float lsum0 = 0.0f, lsum8 = 0.0f;

    unsigned aqh[4][4];
    bool qloaded = false;
    const int qr = rb + (tile & 1) * 8 + trow;

    int buf = 0;
    for (int kt = 0; kt < ntiles; kt++) {
        const int kt0 = kt * 64;
        if (kt + 1 < ntiles) { pref(buf ^ 1, (kt + 1) * 64); cp_commit(); cp_wait<1>(); }
        else cp_wait<0>();
        __syncthreads();

        if (!qloaded) {
            qloaded = true;
#pragma unroll
            for (int kc = 0; kc < 4; kc++)
                ldsm4(aqh[kc], &A_Q[qr * ASLD + kc * 16 + (tile >> 1) * 8]);
        }

        const bf16* KHs = A_KV(buf, 0);
        const bf16* KLs = A_KV(buf, 1);
        const bf16* VHs = A_KV(buf, 2);
        const bf16* VLs = A_KV(buf, 3);

        unsigned pah[4][4], pal[4][4];

#pragma unroll
        for (int half = 0; half < 2; half++) {
            float sc[4][4];
#pragma unroll
            for (int nt = 0; nt < 4; nt++)
#pragma unroll
                for (int i = 0; i < 4; i++) sc[nt][i] = 0.0f;

#pragma unroll
            for (int kc = 0; kc < 4; kc++) {
                const int koff = kc * 16 + (tile & 1) * 8;
                unsigned kbh[2][4], kbl[2][4];
#pragma unroll
                for (int ntp = 0; ntp < 2; ntp++) {
                    const int nrow = (half * 2 + ntp) * 16 + (tile >> 1) * 8 + trow;
                    ldsm4(kbh[ntp], &KHs[nrow * ASLD + koff]);
                    ldsm4(kbl[ntp], &KLs[nrow * ASLD + koff]);
                }
#pragma unroll
                for (int ntp = 0; ntp < 2; ntp++)
#pragma unroll
                    for (int q = 0; q < 2; q++)
                        mma_bf16(sc[ntp * 2 + q], aqh[kc], kbh[ntp][q * 2], kbh[ntp][q * 2 + 1]);
#pragma unroll
                for (int ntp = 0; ntp < 2; ntp++)
#pragma unroll
                    for (int q = 0; q < 2; q++)
                        mma_bf16(sc[ntp * 2 + q], aqh[kc], kbl[ntp][q * 2], kbl[ntp][q * 2 + 1]);
            }

#pragma unroll
            for (int ntl = 0; ntl < 4; ntl++) {
                const int nt = half * 4 + ntl;
                const int kch = nt >> 1, q = nt & 1;
                const int colg = kt0 + nt * 8 + 2 * t;
                const bool v0c = colg < cnt;
                const bool v1c = colg + 1 < cnt;
                float p0 = v0c ? __expf(sc[ntl][0] * scale) : 0.0f;
                float p1 = v1c ? __expf(sc[ntl][1] * scale) : 0.0f;
                float p2 = v0c ? __expf(sc[ntl][2] * scale) : 0.0f;
                float p3 = v1c ? __expf(sc[ntl][3] * scale) : 0.0f;
                lsum0 += p0 + p1;
                lsum8 += p2 + p3;
                bf16 h0, l0, h1, l1, h2, l2, h3, l3;
                split1(p0, h0, l0); split1(p1, h1, l1);
                split1(p2, h2, l2); split1(p3, h3, l3);
                pah[kch][q * 2 + 0] = pack2(h0, h1);
                pah[kch][q * 2 + 1] = pack2(h2, h3);
                pal[kch][q * 2 + 0] = pack2(l0, l1);
                pal[kch][q * 2 + 1] = pack2(l2, l3);
            }
        }

#pragma unroll
        for (int kch = 0; kch < 4; kch++) {
            const int keyrow = kch * 16 + (tile & 1) * 8 + trow;
            unsigned vh[4][4], vl[4][4];
#pragma unroll
            for (int dp = 0; dp < 4; dp++) {
                const int dcol = dp * 16 + (tile >> 1) * 8;
                ldsm4t(vh[dp], &VHs[keyrow * ASLD + dcol]);
                ldsm4t(vl[dp], &VLs[keyrow * ASLD + dcol]);
            }
#pragma unroll
            for (int dp = 0; dp < 4; dp++)
#pragma unroll
                for (int q = 0; q < 2; q++)
                    mma_bf16(O[dp * 2 + q], pah[kch], vh[dp][q * 2], vh[dp][q * 2 + 1]);
#pragma unroll
            for (int dp = 0; dp < 4; dp++)
#pragma unroll
                for (int q = 0; q < 2; q++)
                    mma_bf16(O[dp * 2 + q], pah[kch], vl[dp][q * 2], vl[dp][q * 2 + 1]);
#pragma unroll
            for (int dp = 0; dp < 4; dp++)
#pragma unroll
                for (int q = 0; q < 2; q++)
                    mma_bf16(O[dp * 2 + q], pal[kch], vh[dp][q * 2], vh[dp][q * 2 + 1]);
        }
        __syncthreads();
        buf ^= 1;
    }

    lsum0 += __shfl_xor_sync(0xffffffffu, lsum0, 1);
    lsum0 += __shfl_xor_sync(0xffffffffu, lsum0, 2);
    lsum8 += __shfl_xor_sync(0xffffffffu, lsum8, 1);
    lsum8 += __shfl_xor_sync(0xffffffffu, lsum8, 2);
    const float inv0 = 1.0f / lsum0;
    const float inv8 = 1.0f / lsum8;

    const size_t row0 = (size_t)(b * NN + q0 + rb + g);
    const size_t row8 = row0 + 8;
#pragma unroll
    for (int nt = 0; nt < 8; nt++) {
        const int d = h * 64 + nt * 8 + 2 * t;
        float v0 = O[nt][0] * inv0, v1 = O[nt][1] * inv0;
        float v2 = O[nt][2] * inv8, v3 = O[nt][3] * inv8;
        bf16 h0, l0, h1, l1, h2, l2, h3, l3;
        split1(v0, h0, l0); split1(v1, h1, l1);
        split1(v2, h2, l2); split1(v3, h3, l3);
        *reinterpret_cast<unsigned*>(&g_atc_h[row0 * INNER + d]) = pack2(h0, h1);
        *reinterpret_cast<unsigned*>(&g_atc_l[row0 * INNER + d]) = pack2(l0, l1);
        *reinterpret_cast<unsigned*>(&g_atc_h[row8 * INNER + d]) = pack2(h2, h3);
        *reinterpret_cast<unsigned*>(&g_atc_l[row8 * INNER + d]) = pack2(l2, l3);
    }
}

// ---------------------------------------------------------------------------
extern "C" void kernel_launch(void* const* d_in, const int* in_sizes, int n_in,
                              void* d_out, int out_size)
{
    const float* x     = (const float*)d_in[0];
    const int*   mnp   = (const int*)d_in[1];
    const int*   mbert = (const int*)d_in[2];
    const float* Wqkv  = (const float*)d_in[3];
    const float* Wout  = (const float*)d_in[4];
    const float* bout  = (const float*)d_in[5];
    float* out = (float*)d_out;

    cudaFuncSetAttribute(gemm_proj, cudaFuncAttributeMaxDynamicSharedMemorySize,
                         GEMM_SMEM_BYTES);
    cudaFuncSetAttribute(gemm_out, cudaFuncAttributeMaxDynamicSharedMemorySize,
                         GEMM_SMEM_BYTES);
    cudaFuncSetAttribute(attn_mma, cudaFuncAttributeMaxDynamicSharedMemorySize,
                         ATT_SMEM_BYTES);

    cudaStream_t s2;
    cudaStreamCreateWithFlags(&s2, cudaStreamNonBlocking);
    cudaEvent_t e0, e_bb, e_wout, e_df;
    cudaEventCreateWithFlags(&e0,     cudaEventDisableTiming);
    cudaEventCreateWithFlags(&e_bb,   cudaEventDisableTiming);
    cudaEventCreateWithFlags(&e_wout, cudaEventDisableTiming);
    cudaEventCreateWithFlags(&e_df,   cudaEventDisableTiming);

    // fork
    cudaEventRecord(e0, 0);
    cudaStreamWaitEvent(s2, e0, 0);

    // main stream: split x+Wqkv
    split_xw<<<1024, 256>>>(x, Wqkv);

    // side stream
    build_both<<<dim3(2, BB), 256, 0, s2>>>(mnp, mbert);
    cudaEventRecord(e_bb, s2);
    meanx_part<<<dim3(DIM / 64, BB, 8), dim3(64, 8), 0, s2>>>(x);
    vmean_part<<<dim3(INNER / 64, BB, 8), dim3(64, 8), 0, s2>>>(Wqkv);
    deadvec_fused<<<dim3(DIM / 64, BB), dim3(64, 16), 0, s2>>>(Wout, bout);
    atc_vmean_fill<<<dim3(NN, BB), 128, 0, s2>>>();
    zero_alive<<<dim3(NN, BB), 128, 0, s2>>>(out);
    split_wout<<<128, 256, 0, s2>>>(Wout);
    cudaEventRecord(e_wout, s2);
    dead_fill<<<dim3(NN, BB), 128, 0, s2>>>(out);
    cudaEventRecord(e_df, s2);

    // main stream
    cudaStreamWaitEvent(0, e_bb, 0);
    gemm_proj<<<dim3(12, MROWS / 128), 512, GEMM_SMEM_BYTES>>>();

    attn_mma<<<dim3(NN / 128, BB * HH), 256, ATT_SMEM_BYTES>>>();

    cudaStreamWaitEvent(0, e_wout, 0);
    gemm_out<<<dim3(DIM / 128, MROWS / 128, 2), 512, GEMM_SMEM_BYTES>>>(bout, out);

    // join
    cudaStreamWaitEvent(0, e_df, 0);
}